// round 2
// baseline (speedup 1.0000x reference)
#include <cuda_runtime.h>
#include <math.h>

// Problem constants
#define TSEQ 128
#define HU   64          // LSTM units
#define NG   256         // 4*H gate columns
#define BATCH 2048
#define MTOT (BATCH*TSEQ)   // 262144 rows for the input-projection GEMMs

// Scratch (allowed: __device__ globals, no allocation at runtime)
__device__ float g_xz[(size_t)MTOT * NG];   // 268 MB: xz buffer (reused layer1/layer2)
__device__ float g_h1[(size_t)MTOT * HU];   // 67 MB: layer-1 hidden sequence

// ---------------------------------------------------------------------------
// GEMM: C[M,256] = A[M,K] @ W[K,256] + bias[256]
// Block tile 128x128, 256 threads, 8x8 register tile per thread.
// ---------------------------------------------------------------------------
template <int K>
__global__ __launch_bounds__(256) void gemm_bias_kernel(
    const float* __restrict__ A, const float* __restrict__ W,
    const float* __restrict__ bias, float* __restrict__ C)
{
    __shared__ float As[16][132];   // stored transposed: As[k][m]
    __shared__ float Bs[16][132];   // Bs[k][n]

    const int m0 = blockIdx.x * 128;
    const int n0 = blockIdx.y * 128;
    const int t  = threadIdx.x;
    const int tx = t & 15;          // 0..15 -> n
    const int ty = t >> 4;          // 0..15 -> m

    float acc[8][8];
#pragma unroll
    for (int i = 0; i < 8; i++)
#pragma unroll
        for (int j = 0; j < 8; j++) acc[i][j] = 0.f;

    for (int kc = 0; kc < K; kc += 16) {
        // Load A tile (128 rows x 16 k) -> As[k][m]
#pragma unroll
        for (int i = 0; i < 2; i++) {
            int idx = t + i * 256;       // 0..511, 512 float4 loads
            int row = idx >> 2;          // 0..127
            int q   = idx & 3;           // which float4 along k
            float4 v = *(const float4*)(A + (size_t)(m0 + row) * K + kc + q * 4);
            As[q * 4 + 0][row] = v.x;
            As[q * 4 + 1][row] = v.y;
            As[q * 4 + 2][row] = v.z;
            As[q * 4 + 3][row] = v.w;
        }
        // Load W tile (16 k x 128 n) -> Bs[k][n]
#pragma unroll
        for (int i = 0; i < 2; i++) {
            int idx = t + i * 256;       // 0..511
            int row = idx >> 5;          // 0..15 (k)
            int c4  = idx & 31;          // 0..31 (float4 along n)
            float4 v = *(const float4*)(W + (size_t)(kc + row) * NG + n0 + c4 * 4);
            *(float4*)(&Bs[row][c4 * 4]) = v;
        }
        __syncthreads();

#pragma unroll
        for (int k = 0; k < 16; k++) {
            float4 a0 = *(const float4*)&As[k][ty * 8];
            float4 a1 = *(const float4*)&As[k][ty * 8 + 4];
            float4 b0 = *(const float4*)&Bs[k][tx * 8];
            float4 b1 = *(const float4*)&Bs[k][tx * 8 + 4];
            float a[8] = {a0.x, a0.y, a0.z, a0.w, a1.x, a1.y, a1.z, a1.w};
            float b[8] = {b0.x, b0.y, b0.z, b0.w, b1.x, b1.y, b1.z, b1.w};
#pragma unroll
            for (int i = 0; i < 8; i++)
#pragma unroll
                for (int j = 0; j < 8; j++)
                    acc[i][j] = fmaf(a[i], b[j], acc[i][j]);
        }
        __syncthreads();
    }

    // Epilogue: += bias, vectorized stores
    float4 bv0 = *(const float4*)(bias + n0 + tx * 8);
    float4 bv1 = *(const float4*)(bias + n0 + tx * 8 + 4);
#pragma unroll
    for (int i = 0; i < 8; i++) {
        size_t row = (size_t)(m0 + ty * 8 + i);
        float4 o0, o1;
        o0.x = acc[i][0] + bv0.x; o0.y = acc[i][1] + bv0.y;
        o0.z = acc[i][2] + bv0.z; o0.w = acc[i][3] + bv0.w;
        o1.x = acc[i][4] + bv1.x; o1.y = acc[i][5] + bv1.y;
        o1.z = acc[i][6] + bv1.z; o1.w = acc[i][7] + bv1.w;
        *(float4*)(C + row * NG + n0 + tx * 8)     = o0;
        *(float4*)(C + row * NG + n0 + tx * 8 + 4) = o1;
    }
}

// ---------------------------------------------------------------------------
// Recurrent kernel. One block handles TB=8 batch rows for all 128 timesteps.
// 256 threads: thread j owns gate column j; U[:,j] kept in 64 registers.
// h broadcast through shared (float4), gates combined by threads j<64.
// ACT: 0 = tanh (layer 1), 1 = sigmoid (layer 2).
// hout layout: hout[((b*T + t)*H) + u]  (== output reshape for layer 2).
// ---------------------------------------------------------------------------
__device__ __forceinline__ float sigf(float x) {
    return 1.f / (1.f + __expf(-x));
}

template <int ACT>
__global__ __launch_bounds__(256) void lstm_rec_kernel(
    const float* __restrict__ xz, const float* __restrict__ U,
    float* __restrict__ hout)
{
    const int TB = 8;
    __shared__ float4 h4[TB][16];       // h state, [tb][k/4]
    __shared__ float  z_sh[TB][NG];     // gate pre-activations

    const int j  = threadIdx.x;         // gate column 0..255
    const int b0 = blockIdx.x * TB;

    // Recurrent weights column j in registers (64 regs)
    float u[HU];
#pragma unroll
    for (int k = 0; k < HU; k++) u[k] = U[(size_t)k * NG + j];

    // Zero init state
    if (j < TB * 16) ((float4*)h4)[j] = make_float4(0.f, 0.f, 0.f, 0.f);
    float c[TB];
#pragma unroll
    for (int tb = 0; tb < TB; tb++) c[tb] = 0.f;
    __syncthreads();

    const float* xb = xz + (size_t)b0 * TSEQ * NG + j;

    for (int t = 0; t < TSEQ; t++) {
        float acc[TB];
#pragma unroll
        for (int tb = 0; tb < TB; tb++)
            acc[tb] = xb[(size_t)(tb * TSEQ + t) * NG];

#pragma unroll
        for (int k4 = 0; k4 < 16; k4++) {
#pragma unroll
            for (int tb = 0; tb < TB; tb++) {
                float4 hv = h4[tb][k4];     // broadcast, conflict-free
                acc[tb] = fmaf(hv.x, u[k4 * 4 + 0], acc[tb]);
                acc[tb] = fmaf(hv.y, u[k4 * 4 + 1], acc[tb]);
                acc[tb] = fmaf(hv.z, u[k4 * 4 + 2], acc[tb]);
                acc[tb] = fmaf(hv.w, u[k4 * 4 + 3], acc[tb]);
            }
        }
#pragma unroll
        for (int tb = 0; tb < TB; tb++) z_sh[tb][j] = acc[tb];
        __syncthreads();

        if (j < HU) {
#pragma unroll
            for (int tb = 0; tb < TB; tb++) {
                float zi = z_sh[tb][j];
                float zf = z_sh[tb][j + 64];
                float zg = z_sh[tb][j + 128];
                float zo = z_sh[tb][j + 192];
                float ig = sigf(zi);
                float fg = sigf(zf);
                float gg = (ACT == 0) ? tanhf(zg) : sigf(zg);
                float og = sigf(zo);
                c[tb] = fmaf(fg, c[tb], ig * gg);
                float ca = (ACT == 0) ? tanhf(c[tb]) : sigf(c[tb]);
                float h = og * ca;
                ((float*)h4)[tb * HU + j] = h;
                hout[((size_t)(b0 + tb) * TSEQ + t) * HU + j] = h;
            }
        }
        __syncthreads();
    }
}

// ---------------------------------------------------------------------------
// Launch
// ---------------------------------------------------------------------------
extern "C" void kernel_launch(void* const* d_in, const int* in_sizes, int n_in,
                              void* d_out, int out_size)
{
    const float* x  = (const float*)d_in[0];
    const float* W1 = (const float*)d_in[1];
    const float* U1 = (const float*)d_in[2];
    const float* b1 = (const float*)d_in[3];
    const float* W2 = (const float*)d_in[4];
    const float* U2 = (const float*)d_in[5];
    const float* b2 = (const float*)d_in[6];
    float* out = (float*)d_out;

    void *xz_p = nullptr, *h1_p = nullptr;
    cudaGetSymbolAddress(&xz_p, g_xz);
    cudaGetSymbolAddress(&h1_p, g_h1);
    float* xz = (float*)xz_p;
    float* h1 = (float*)h1_p;

    dim3 ggrid(MTOT / 128, 2);

    // Layer 1
    gemm_bias_kernel<128><<<ggrid, 256>>>(x, W1, b1, xz);
    lstm_rec_kernel<0><<<BATCH / 8, 256>>>(xz, U1, h1);

    // Layer 2 (input = h1, K=64)
    gemm_bias_kernel<64><<<ggrid, 256>>>(h1, W2, b2, xz);
    lstm_rec_kernel<1><<<BATCH / 8, 256>>>(xz, U2, out);
}

// round 3
// speedup vs baseline: 1.4214x; 1.4214x over previous
#include <cuda_runtime.h>
#include <math.h>

// Problem constants
#define TSEQ 128
#define HU   64          // LSTM units
#define NG   256         // 4*H gate columns
#define BATCH 2048
#define MTOT (BATCH*TSEQ)   // 262144 rows for input-projection GEMMs

typedef unsigned long long u64;

// Scratch (__device__ globals: the allowed scratch mechanism)
__device__ float g_xz[(size_t)MTOT * NG];   // 268 MB xz buffer (reused by both layers)
__device__ float g_h1[(size_t)MTOT * HU];   // 67 MB layer-1 hidden sequence

// ---------------------------------------------------------------------------
// f32x2 packed-FMA helpers (FFMA2: 2x fp32 throughput, PTX-only path)
// ---------------------------------------------------------------------------
__device__ __forceinline__ u64 pack2(float lo, float hi) {
    u64 r; asm("mov.b64 %0, {%1, %2};" : "=l"(r) : "f"(lo), "f"(hi)); return r;
}
__device__ __forceinline__ void unpack2(u64 v, float& lo, float& hi) {
    asm("mov.b64 {%0, %1}, %2;" : "=f"(lo), "=f"(hi) : "l"(v));
}
__device__ __forceinline__ u64 fma2(u64 a, u64 b, u64 c) {
    u64 r; asm("fma.rn.f32x2 %0, %1, %2, %3;" : "=l"(r) : "l"(a), "l"(b), "l"(c));
    return r;
}

// ---------------------------------------------------------------------------
// GEMM: C[M,256] = A[M,K] @ W[K,256] + bias. 128x128 tile, 256 thr, 8x8/thread,
// accumulators held as f32x2 pairs (FFMA2).
// ---------------------------------------------------------------------------
template <int K>
__global__ __launch_bounds__(256) void gemm_bias_kernel(
    const float* __restrict__ A, const float* __restrict__ W,
    const float* __restrict__ bias, float* __restrict__ C)
{
    __shared__ float As[16][132];   // As[k][m]
    __shared__ float Bs[16][132];   // Bs[k][n]

    const int m0 = blockIdx.x * 128;
    const int n0 = blockIdx.y * 128;
    const int t  = threadIdx.x;
    const int tx = t & 15;          // n
    const int ty = t >> 4;          // m

    u64 acc2[8][4];
#pragma unroll
    for (int i = 0; i < 8; i++)
#pragma unroll
        for (int j = 0; j < 4; j++) acc2[i][j] = 0ull;

    for (int kc = 0; kc < K; kc += 16) {
#pragma unroll
        for (int i = 0; i < 2; i++) {
            int idx = t + i * 256;
            int row = idx >> 2;
            int q   = idx & 3;
            float4 v = *(const float4*)(A + (size_t)(m0 + row) * K + kc + q * 4);
            As[q * 4 + 0][row] = v.x;
            As[q * 4 + 1][row] = v.y;
            As[q * 4 + 2][row] = v.z;
            As[q * 4 + 3][row] = v.w;
        }
#pragma unroll
        for (int i = 0; i < 2; i++) {
            int idx = t + i * 256;
            int row = idx >> 5;
            int c4  = idx & 31;
            float4 v = *(const float4*)(W + (size_t)(kc + row) * NG + n0 + c4 * 4);
            *(float4*)(&Bs[row][c4 * 4]) = v;
        }
        __syncthreads();

#pragma unroll
        for (int k = 0; k < 16; k++) {
            float4 a0 = *(const float4*)&As[k][ty * 8];
            float4 a1 = *(const float4*)&As[k][ty * 8 + 4];
            float a[8] = {a0.x, a0.y, a0.z, a0.w, a1.x, a1.y, a1.z, a1.w};
            u64 b2[4];
#pragma unroll
            for (int j = 0; j < 4; j++)
                b2[j] = *(const u64*)&Bs[k][tx * 8 + j * 2];
#pragma unroll
            for (int i = 0; i < 8; i++) {
                u64 as = pack2(a[i], a[i]);
#pragma unroll
                for (int j = 0; j < 4; j++)
                    acc2[i][j] = fma2(as, b2[j], acc2[i][j]);
            }
        }
        __syncthreads();
    }

    float4 bv0 = *(const float4*)(bias + n0 + tx * 8);
    float4 bv1 = *(const float4*)(bias + n0 + tx * 8 + 4);
    float bb[8] = {bv0.x, bv0.y, bv0.z, bv0.w, bv1.x, bv1.y, bv1.z, bv1.w};
#pragma unroll
    for (int i = 0; i < 8; i++) {
        size_t row = (size_t)(m0 + ty * 8 + i);
        float o[8];
#pragma unroll
        for (int j = 0; j < 4; j++) {
            float lo, hi; unpack2(acc2[i][j], lo, hi);
            o[j * 2]     = lo + bb[j * 2];
            o[j * 2 + 1] = hi + bb[j * 2 + 1];
        }
        *(float4*)(C + row * NG + n0 + tx * 8)     = make_float4(o[0], o[1], o[2], o[3]);
        *(float4*)(C + row * NG + n0 + tx * 8 + 4) = make_float4(o[4], o[5], o[6], o[7]);
    }
}

// ---------------------------------------------------------------------------
// Recurrent kernel v2.
//  - TB=8 batch rows/block, 256 blocks, 256 threads.
//  - Matvec: thread j owns gate column j, U[:,j] in 64 regs; h stored k-major
//    in shared (h_sh[k][tb]) so tb-pairs load as f32x2 via LDS.64; FFMA2.
//  - xz for step t+1 prefetched into registers during step t.
//  - Epilogue spread over ALL 256 threads (2 gate tasks each), MUFU-based
//    sigmoid/tanh (__expf + __frcp), c-state in registers.
// ACT: 0 = tanh (layer 1), 1 = sigmoid (layer 2).
// ---------------------------------------------------------------------------
__device__ __forceinline__ float sigf(float x) {
    return __frcp_rn(1.f + __expf(-x));
}
__device__ __forceinline__ float tanf_fast(float x) {
    // tanh(x) = 2/(1+exp(-2x)) - 1
    return fmaf(2.f, __frcp_rn(1.f + __expf(-2.f * x)), -1.f);
}

template <int ACT>
__global__ __launch_bounds__(256) void lstm_rec_kernel(
    const float* __restrict__ xz, const float* __restrict__ U,
    float* __restrict__ hout)
{
    const int TB = 8;
    __shared__ float h_sh[HU][10];      // k-major h; pad 10 keeps u64 pairs aligned
    __shared__ float z_sh[TB][NG];      // gate pre-activations

    const int j  = threadIdx.x;         // gate column 0..255
    const int b0 = blockIdx.x * TB;

    // U column j in registers
    float u[HU];
#pragma unroll
    for (int k = 0; k < HU; k++) u[k] = U[(size_t)k * NG + j];

    // zero h state
    for (int i = j; i < HU * 10; i += 256) ((float*)h_sh)[i] = 0.f;

    // epilogue ownership: thread -> (tbA, jc) and (tbA+4, jc)
    const int jc  = j & 63;
    const int tbA = j >> 6;             // 0..3
    float c0 = 0.f, c1 = 0.f;

    const float* xb = xz + (size_t)b0 * TSEQ * NG + j;

    // prefetch xz for t=0
    float xn[TB];
#pragma unroll
    for (int tb = 0; tb < TB; tb++)
        xn[tb] = xb[(size_t)(tb * TSEQ) * NG];

    __syncthreads();

    for (int t = 0; t < TSEQ; t++) {
        // stage current, prefetch next step
        u64 acc2[4];
#pragma unroll
        for (int p = 0; p < 4; p++) acc2[p] = pack2(xn[2 * p], xn[2 * p + 1]);
        if (t + 1 < TSEQ) {
#pragma unroll
            for (int tb = 0; tb < TB; tb++)
                xn[tb] = xb[(size_t)(tb * TSEQ + t + 1) * NG];
        }

        // matvec: z[tb][j] += sum_k h[tb][k] * U[k][j]   (f32x2 over tb-pairs)
#pragma unroll
        for (int k = 0; k < HU; k++) {
            u64 uk = pack2(u[k], u[k]);
            u64 h01 = *(const u64*)&h_sh[k][0];
            u64 h23 = *(const u64*)&h_sh[k][2];
            u64 h45 = *(const u64*)&h_sh[k][4];
            u64 h67 = *(const u64*)&h_sh[k][6];
            acc2[0] = fma2(h01, uk, acc2[0]);
            acc2[1] = fma2(h23, uk, acc2[1]);
            acc2[2] = fma2(h45, uk, acc2[2]);
            acc2[3] = fma2(h67, uk, acc2[3]);
        }
#pragma unroll
        for (int p = 0; p < 4; p++) {
            float lo, hi; unpack2(acc2[p], lo, hi);
            z_sh[2 * p][j]     = lo;
            z_sh[2 * p + 1][j] = hi;
        }
        __syncthreads();

        // epilogue: all threads, 2 (tb, jc) tasks each
#pragma unroll
        for (int task = 0; task < 2; task++) {
            int tb = tbA + task * 4;
            float zi = z_sh[tb][jc];
            float zf = z_sh[tb][jc + 64];
            float zg = z_sh[tb][jc + 128];
            float zo = z_sh[tb][jc + 192];
            float ig = sigf(zi);
            float fg = sigf(zf);
            float gg = (ACT == 0) ? tanf_fast(zg) : sigf(zg);
            float og = sigf(zo);
            float& c = task ? c1 : c0;
            c = fmaf(fg, c, ig * gg);
            float ca = (ACT == 0) ? tanf_fast(c) : sigf(c);
            float h = og * ca;
            h_sh[jc][tb] = h;
            hout[((size_t)(b0 + tb) * TSEQ + t) * HU + jc] = h;
        }
        __syncthreads();
    }
}

// ---------------------------------------------------------------------------
// Launch
// ---------------------------------------------------------------------------
extern "C" void kernel_launch(void* const* d_in, const int* in_sizes, int n_in,
                              void* d_out, int out_size)
{
    const float* x  = (const float*)d_in[0];
    const float* W1 = (const float*)d_in[1];
    const float* U1 = (const float*)d_in[2];
    const float* b1 = (const float*)d_in[3];
    const float* W2 = (const float*)d_in[4];
    const float* U2 = (const float*)d_in[5];
    const float* b2 = (const float*)d_in[6];
    float* out = (float*)d_out;

    void *xz_p = nullptr, *h1_p = nullptr;
    cudaGetSymbolAddress(&xz_p, g_xz);
    cudaGetSymbolAddress(&h1_p, g_h1);
    float* xz = (float*)xz_p;
    float* h1 = (float*)h1_p;

    dim3 ggrid(MTOT / 128, 2);

    // Layer 1
    gemm_bias_kernel<128><<<ggrid, 256>>>(x, W1, b1, xz);
    lstm_rec_kernel<0><<<BATCH / 8, 256>>>(xz, U1, h1);

    // Layer 2 (input = h1, K=64)
    gemm_bias_kernel<64><<<ggrid, 256>>>(h1, W2, b2, xz);
    lstm_rec_kernel<1><<<BATCH / 8, 256>>>(xz, U2, out);
}

// round 4
// speedup vs baseline: 1.5025x; 1.0571x over previous
#include <cuda_runtime.h>
#include <math.h>

// Problem constants
#define TSEQ 128
#define HU   64          // LSTM units
#define NG   256         // 4*H gate columns
#define BATCH 2048
#define MTOT (BATCH*TSEQ)   // 262144 rows for input-projection GEMMs

typedef unsigned long long u64;

// Scratch (__device__ globals: the allowed scratch mechanism)
__device__ float g_xz[(size_t)MTOT * NG];   // 268 MB xz buffer (reused by both layers)
__device__ float g_h1[(size_t)MTOT * HU];   // 67 MB layer-1 hidden sequence

// ---------------------------------------------------------------------------
// f32x2 packed-FMA helpers (FFMA2: 2x fp32 throughput, PTX-only path)
// ---------------------------------------------------------------------------
__device__ __forceinline__ u64 pack2(float lo, float hi) {
    u64 r; asm("mov.b64 %0, {%1, %2};" : "=l"(r) : "f"(lo), "f"(hi)); return r;
}
__device__ __forceinline__ void unpack2(u64 v, float& lo, float& hi) {
    asm("mov.b64 {%0, %1}, %2;" : "=f"(lo), "=f"(hi) : "l"(v));
}
__device__ __forceinline__ u64 fma2(u64 a, u64 b, u64 c) {
    u64 r; asm("fma.rn.f32x2 %0, %1, %2, %3;" : "=l"(r) : "l"(a), "l"(b), "l"(c));
    return r;
}

// HW tanh (MUFU.TANH, sm_75+). sigmoid(x) = 0.5*tanh(0.5x)+0.5
__device__ __forceinline__ float tanh_ap(float x) {
    float y; asm("tanh.approx.f32 %0, %1;" : "=f"(y) : "f"(x)); return y;
}
__device__ __forceinline__ float sig_ap(float x) {
    return fmaf(0.5f, tanh_ap(0.5f * x), 0.5f);
}

// ---------------------------------------------------------------------------
// GEMM: C[M,256] = A[M,K] @ W[K,256] + bias. 128x128 tile, 256 thr, 8x8/thread,
// FFMA2 accumulators; B operand read as LDS.128 pairs.
// ---------------------------------------------------------------------------
template <int K>
__global__ __launch_bounds__(256) void gemm_bias_kernel(
    const float* __restrict__ A, const float* __restrict__ W,
    const float* __restrict__ bias, float* __restrict__ C)
{
    __shared__ __align__(16) float As[16][132];   // As[k][m]  (132*4 = 528 B, 16B-mult)
    __shared__ __align__(16) float Bs[16][132];   // Bs[k][n]

    const int m0 = blockIdx.x * 128;
    const int n0 = blockIdx.y * 128;
    const int t  = threadIdx.x;
    const int tx = t & 15;          // n
    const int ty = t >> 4;          // m

    u64 acc2[8][4];
#pragma unroll
    for (int i = 0; i < 8; i++)
#pragma unroll
        for (int j = 0; j < 4; j++) acc2[i][j] = 0ull;

    for (int kc = 0; kc < K; kc += 16) {
#pragma unroll
        for (int i = 0; i < 2; i++) {
            int idx = t + i * 256;
            int row = idx >> 2;
            int q   = idx & 3;
            float4 v = *(const float4*)(A + (size_t)(m0 + row) * K + kc + q * 4);
            As[q * 4 + 0][row] = v.x;
            As[q * 4 + 1][row] = v.y;
            As[q * 4 + 2][row] = v.z;
            As[q * 4 + 3][row] = v.w;
        }
#pragma unroll
        for (int i = 0; i < 2; i++) {
            int idx = t + i * 256;
            int row = idx >> 5;
            int c4  = idx & 31;
            float4 v = *(const float4*)(W + (size_t)(kc + row) * NG + n0 + c4 * 4);
            *(float4*)(&Bs[row][c4 * 4]) = v;
        }
        __syncthreads();

#pragma unroll
        for (int k = 0; k < 16; k++) {
            float4 a0 = *(const float4*)&As[k][ty * 8];
            float4 a1 = *(const float4*)&As[k][ty * 8 + 4];
            float a[8] = {a0.x, a0.y, a0.z, a0.w, a1.x, a1.y, a1.z, a1.w};
            ulonglong2 bA = *(const ulonglong2*)&Bs[k][tx * 8];
            ulonglong2 bB = *(const ulonglong2*)&Bs[k][tx * 8 + 4];
            u64 b2[4] = {bA.x, bA.y, bB.x, bB.y};
#pragma unroll
            for (int i = 0; i < 8; i++) {
                u64 as = pack2(a[i], a[i]);
#pragma unroll
                for (int j = 0; j < 4; j++)
                    acc2[i][j] = fma2(as, b2[j], acc2[i][j]);
            }
        }
        __syncthreads();
    }

    float4 bv0 = *(const float4*)(bias + n0 + tx * 8);
    float4 bv1 = *(const float4*)(bias + n0 + tx * 8 + 4);
    float bb[8] = {bv0.x, bv0.y, bv0.z, bv0.w, bv1.x, bv1.y, bv1.z, bv1.w};
#pragma unroll
    for (int i = 0; i < 8; i++) {
        size_t row = (size_t)(m0 + ty * 8 + i);
        float o[8];
#pragma unroll
        for (int j = 0; j < 4; j++) {
            float lo, hi; unpack2(acc2[i][j], lo, hi);
            o[j * 2]     = lo + bb[j * 2];
            o[j * 2 + 1] = hi + bb[j * 2 + 1];
        }
        *(float4*)(C + row * NG + n0 + tx * 8)     = make_float4(o[0], o[1], o[2], o[3]);
        *(float4*)(C + row * NG + n0 + tx * 8 + 4) = make_float4(o[4], o[5], o[6], o[7]);
    }
}

// ---------------------------------------------------------------------------
// Recurrent kernel v3.
//  - TB=8 batch rows/block, 256 blocks, 256 threads.
//  - Matvec: thread j owns gate column j, U[:,j] in 64 regs; h k-major in
//    shared as h_sh[k][0..7] so the 8 tb values load as TWO LDS.128
//    (ulonglong2 = two f32x2 pairs each) -> 128 broadcast LDS/step (was 256).
//  - xz for step t+1 prefetched into registers during step t.
//  - Epilogue over all 256 threads, MUFU.TANH activations.
// ACT: 0 = tanh (layer 1), 1 = sigmoid (layer 2).
// ---------------------------------------------------------------------------
template <int ACT>
__global__ __launch_bounds__(256) void lstm_rec_kernel(
    const float* __restrict__ xz, const float* __restrict__ U,
    float* __restrict__ hout)
{
    const int TB = 8;
    __shared__ __align__(16) float h_sh[HU][TB];   // k-major h; row = 32 B
    __shared__ float z_sh[TB][NG];                 // gate pre-activations

    const int j  = threadIdx.x;         // gate column 0..255
    const int b0 = blockIdx.x * TB;

    // U column j in registers
    float u[HU];
#pragma unroll
    for (int k = 0; k < HU; k++) u[k] = U[(size_t)k * NG + j];

    // zero h state
    if (j < HU * TB / 4) ((float4*)h_sh)[j] = make_float4(0.f, 0.f, 0.f, 0.f);

    // epilogue ownership: thread -> (tbA, jc) and (tbA+4, jc)
    const int jc  = j & 63;
    const int tbA = j >> 6;             // 0..3
    float c0 = 0.f, c1 = 0.f;

    const float* xb = xz + (size_t)b0 * TSEQ * NG + j;

    // prefetch xz for t=0
    float xn[TB];
#pragma unroll
    for (int tb = 0; tb < TB; tb++)
        xn[tb] = xb[(size_t)(tb * TSEQ) * NG];

    __syncthreads();

    for (int t = 0; t < TSEQ; t++) {
        // stage current, prefetch next step
        u64 acc2[4];
#pragma unroll
        for (int p = 0; p < 4; p++) acc2[p] = pack2(xn[2 * p], xn[2 * p + 1]);
        if (t + 1 < TSEQ) {
#pragma unroll
            for (int tb = 0; tb < TB; tb++)
                xn[tb] = xb[(size_t)(tb * TSEQ + t + 1) * NG];
        }

        // matvec: z[tb][j] += sum_k h[tb][k] * U[k][j]
        // two broadcast LDS.128 per k -> 4 f32x2 pairs
#pragma unroll
        for (int k = 0; k < HU; k++) {
            u64 uk = pack2(u[k], u[k]);
            ulonglong2 hA = *(const ulonglong2*)&h_sh[k][0];   // (h0,h1),(h2,h3)
            ulonglong2 hB = *(const ulonglong2*)&h_sh[k][4];   // (h4,h5),(h6,h7)
            acc2[0] = fma2(hA.x, uk, acc2[0]);
            acc2[1] = fma2(hA.y, uk, acc2[1]);
            acc2[2] = fma2(hB.x, uk, acc2[2]);
            acc2[3] = fma2(hB.y, uk, acc2[3]);
        }
#pragma unroll
        for (int p = 0; p < 4; p++) {
            float lo, hi; unpack2(acc2[p], lo, hi);
            z_sh[2 * p][j]     = lo;
            z_sh[2 * p + 1][j] = hi;
        }
        __syncthreads();

        // epilogue: all threads, 2 (tb, jc) tasks each
#pragma unroll
        for (int task = 0; task < 2; task++) {
            int tb = tbA + task * 4;
            float zi = z_sh[tb][jc];
            float zf = z_sh[tb][jc + 64];
            float zg = z_sh[tb][jc + 128];
            float zo = z_sh[tb][jc + 192];
            float ig = sig_ap(zi);
            float fg = sig_ap(zf);
            float gg = (ACT == 0) ? tanh_ap(zg) : sig_ap(zg);
            float og = sig_ap(zo);
            float& c = task ? c1 : c0;
            c = fmaf(fg, c, ig * gg);
            float ca = (ACT == 0) ? tanh_ap(c) : sig_ap(c);
            float h = og * ca;
            h_sh[jc][tb] = h;
            hout[((size_t)(b0 + tb) * TSEQ + t) * HU + jc] = h;
        }
        __syncthreads();
    }
}

// ---------------------------------------------------------------------------
// Launch
// ---------------------------------------------------------------------------
extern "C" void kernel_launch(void* const* d_in, const int* in_sizes, int n_in,
                              void* d_out, int out_size)
{
    const float* x  = (const float*)d_in[0];
    const float* W1 = (const float*)d_in[1];
    const float* U1 = (const float*)d_in[2];
    const float* b1 = (const float*)d_in[3];
    const float* W2 = (const float*)d_in[4];
    const float* U2 = (const float*)d_in[5];
    const float* b2 = (const float*)d_in[6];
    float* out = (float*)d_out;

    void *xz_p = nullptr, *h1_p = nullptr;
    cudaGetSymbolAddress(&xz_p, g_xz);
    cudaGetSymbolAddress(&h1_p, g_h1);
    float* xz = (float*)xz_p;
    float* h1 = (float*)h1_p;

    dim3 ggrid(MTOT / 128, 2);

    // Layer 1
    gemm_bias_kernel<128><<<ggrid, 256>>>(x, W1, b1, xz);
    lstm_rec_kernel<0><<<BATCH / 8, 256>>>(xz, U1, h1);

    // Layer 2 (input = h1, K=64)
    gemm_bias_kernel<64><<<ggrid, 256>>>(h1, W2, b2, xz);
    lstm_rec_kernel<1><<<BATCH / 8, 256>>>(xz, U2, out);
}

// round 5
// speedup vs baseline: 1.6651x; 1.1082x over previous
#include <cuda_runtime.h>
#include <math.h>

// Problem constants
#define TSEQ 128
#define HU   64          // LSTM units
#define NG   256         // 4*H gate columns
#define BATCH 2048
#define MTOT (BATCH*TSEQ)   // 262144 rows for input-projection GEMMs

typedef unsigned long long u64;

// Scratch (__device__ globals: the allowed scratch mechanism)
__device__ float g_xz[(size_t)MTOT * NG];   // 268 MB xz buffer (reused by both layers)
__device__ float g_h1[(size_t)MTOT * HU];   // 67 MB layer-1 hidden sequence

// ---------------------------------------------------------------------------
// f32x2 packed-FMA helpers (FFMA2: 2x fp32 throughput, PTX-only path)
// ---------------------------------------------------------------------------
__device__ __forceinline__ u64 pack2(float lo, float hi) {
    u64 r; asm("mov.b64 %0, {%1, %2};" : "=l"(r) : "f"(lo), "f"(hi)); return r;
}
__device__ __forceinline__ void unpack2(u64 v, float& lo, float& hi) {
    asm("mov.b64 {%0, %1}, %2;" : "=f"(lo), "=f"(hi) : "l"(v));
}
__device__ __forceinline__ u64 fma2(u64 a, u64 b, u64 c) {
    u64 r; asm("fma.rn.f32x2 %0, %1, %2, %3;" : "=l"(r) : "l"(a), "l"(b), "l"(c));
    return r;
}

// HW tanh (MUFU.TANH). sigmoid(x) = 0.5*tanh(0.5x)+0.5
__device__ __forceinline__ float tanh_ap(float x) {
    float y; asm("tanh.approx.f32 %0, %1;" : "=f"(y) : "f"(x)); return y;
}
__device__ __forceinline__ float sig_ap(float x) {
    return fmaf(0.5f, tanh_ap(0.5f * x), 0.5f);
}

// ---------------------------------------------------------------------------
// GEMM: C[M,256] = A[M,K] @ W[K,256] + bias. 128x128 tile, 256 thr, 8x8/thread,
// FFMA2 accumulators, software-pipelined global->smem loads.
// ---------------------------------------------------------------------------
template <int K>
__global__ __launch_bounds__(256) void gemm_bias_kernel(
    const float* __restrict__ A, const float* __restrict__ W,
    const float* __restrict__ bias, float* __restrict__ C)
{
    __shared__ __align__(16) float As[16][132];   // As[k][m]
    __shared__ __align__(16) float Bs[16][132];   // Bs[k][n]

    const int m0 = blockIdx.x * 128;
    const int n0 = blockIdx.y * 128;
    const int t  = threadIdx.x;
    const int tx = t & 15;          // n
    const int ty = t >> 4;          // m

    // Loader indices (2 float4 each for A and B)
    int aRow[2], aQ[2], bRow[2], bC4[2];
#pragma unroll
    for (int i = 0; i < 2; i++) {
        int idx = t + i * 256;
        aRow[i] = idx >> 2;  aQ[i]  = idx & 3;
        bRow[i] = idx >> 5;  bC4[i] = idx & 31;
    }

    u64 acc2[8][4];
#pragma unroll
    for (int i = 0; i < 8; i++)
#pragma unroll
        for (int j = 0; j < 4; j++) acc2[i][j] = 0ull;

    // Prologue: load tile kc=0 into registers
    float4 aReg[2], bReg[2];
#pragma unroll
    for (int i = 0; i < 2; i++) {
        aReg[i] = *(const float4*)(A + (size_t)(m0 + aRow[i]) * K + aQ[i] * 4);
        bReg[i] = *(const float4*)(W + (size_t)bRow[i] * NG + n0 + bC4[i] * 4);
    }

    for (int kc = 0; kc < K; kc += 16) {
        // Commit staged registers to shared
#pragma unroll
        for (int i = 0; i < 2; i++) {
            As[aQ[i] * 4 + 0][aRow[i]] = aReg[i].x;
            As[aQ[i] * 4 + 1][aRow[i]] = aReg[i].y;
            As[aQ[i] * 4 + 2][aRow[i]] = aReg[i].z;
            As[aQ[i] * 4 + 3][aRow[i]] = aReg[i].w;
            *(float4*)(&Bs[bRow[i]][bC4[i] * 4]) = bReg[i];
        }
        __syncthreads();

        // Prefetch next tile while computing this one
        if (kc + 16 < K) {
#pragma unroll
            for (int i = 0; i < 2; i++) {
                aReg[i] = *(const float4*)(A + (size_t)(m0 + aRow[i]) * K + (kc + 16) + aQ[i] * 4);
                bReg[i] = *(const float4*)(W + (size_t)(kc + 16 + bRow[i]) * NG + n0 + bC4[i] * 4);
            }
        }

#pragma unroll
        for (int k = 0; k < 16; k++) {
            float4 a0 = *(const float4*)&As[k][ty * 8];
            float4 a1 = *(const float4*)&As[k][ty * 8 + 4];
            float a[8] = {a0.x, a0.y, a0.z, a0.w, a1.x, a1.y, a1.z, a1.w};
            ulonglong2 bA = *(const ulonglong2*)&Bs[k][tx * 8];
            ulonglong2 bB = *(const ulonglong2*)&Bs[k][tx * 8 + 4];
            u64 b2[4] = {bA.x, bA.y, bB.x, bB.y};
#pragma unroll
            for (int i = 0; i < 8; i++) {
                u64 as = pack2(a[i], a[i]);
#pragma unroll
                for (int j = 0; j < 4; j++)
                    acc2[i][j] = fma2(as, b2[j], acc2[i][j]);
            }
        }
        __syncthreads();
    }

    float4 bv0 = *(const float4*)(bias + n0 + tx * 8);
    float4 bv1 = *(const float4*)(bias + n0 + tx * 8 + 4);
    float bb[8] = {bv0.x, bv0.y, bv0.z, bv0.w, bv1.x, bv1.y, bv1.z, bv1.w};
#pragma unroll
    for (int i = 0; i < 8; i++) {
        size_t row = (size_t)(m0 + ty * 8 + i);
        float o[8];
#pragma unroll
        for (int j = 0; j < 4; j++) {
            float lo, hi; unpack2(acc2[i][j], lo, hi);
            o[j * 2]     = lo + bb[j * 2];
            o[j * 2 + 1] = hi + bb[j * 2 + 1];
        }
        *(float4*)(C + row * NG + n0 + tx * 8)     = make_float4(o[0], o[1], o[2], o[3]);
        *(float4*)(C + row * NG + n0 + tx * 8 + 4) = make_float4(o[4], o[5], o[6], o[7]);
    }
}

// ---------------------------------------------------------------------------
// Recurrent kernel v4.
//  - TB=8 batch rows/block, 256 blocks, **128 threads**.
//  - Each thread owns TWO gate columns (j and j+128): the same h reads feed
//    2x the FMA2 work -> per-block shared-memory traffic HALVED.
//  - h k-major in shared, read as 2x LDS.128 per k (4 f32x2 tb-pairs).
//  - xz for step t+1 prefetched into registers during step t.
//  - z written as u64 pairs (STS.64); epilogue: 4 (tb, jc) tasks per thread,
//    MUFU.TANH activations, c-state in registers.
// ACT: 0 = tanh (layer 1), 1 = sigmoid (layer 2).
// ---------------------------------------------------------------------------
template <int ACT>
__global__ __launch_bounds__(128) void lstm_rec_kernel(
    const float* __restrict__ xz, const float* __restrict__ U,
    float* __restrict__ hout)
{
    const int TB = 8;
    __shared__ __align__(16) float h_sh[HU][TB];   // k-major h
    __shared__ __align__(16) u64 z2[4][NG];        // [tb/2][gatecol]: (tb even, tb odd)

    const int j  = threadIdx.x;         // first gate column 0..127
    const int j2 = j + 128;             // second gate column
    const int b0 = blockIdx.x * TB;

    // U columns j and j+128 in registers
    float u0[HU], u1[HU];
#pragma unroll
    for (int k = 0; k < HU; k++) {
        u0[k] = U[(size_t)k * NG + j];
        u1[k] = U[(size_t)k * NG + j2];
    }

    // zero h state
    if (j < HU * TB / 4) ((float4*)h_sh)[j] = make_float4(0.f, 0.f, 0.f, 0.f);

    // epilogue ownership: thread j -> jc = j&63, parity tbA = j>>6 (0/1),
    // tasks tb = tbA + 2*s, s = 0..3
    const int jc  = j & 63;
    const int tbA = j >> 6;
    float c[4] = {0.f, 0.f, 0.f, 0.f};

    const float* xb = xz + (size_t)b0 * TSEQ * NG;

    // prefetch xz for t=0 (both columns)
    float xn0[TB], xn1[TB];
#pragma unroll
    for (int tb = 0; tb < TB; tb++) {
        xn0[tb] = xb[(size_t)(tb * TSEQ) * NG + j];
        xn1[tb] = xb[(size_t)(tb * TSEQ) * NG + j2];
    }

    __syncthreads();

    for (int t = 0; t < TSEQ; t++) {
        // stage current step, prefetch next
        u64 a0[4], a1[4];
#pragma unroll
        for (int p = 0; p < 4; p++) {
            a0[p] = pack2(xn0[2 * p], xn0[2 * p + 1]);
            a1[p] = pack2(xn1[2 * p], xn1[2 * p + 1]);
        }
        if (t + 1 < TSEQ) {
#pragma unroll
            for (int tb = 0; tb < TB; tb++) {
                xn0[tb] = xb[(size_t)(tb * TSEQ + t + 1) * NG + j];
                xn1[tb] = xb[(size_t)(tb * TSEQ + t + 1) * NG + j2];
            }
        }

        // matvec: 2 LDS.128 per k feed 8 FMA2 (two gate columns)
#pragma unroll
        for (int k = 0; k < HU; k++) {
            u64 uk0 = pack2(u0[k], u0[k]);
            u64 uk1 = pack2(u1[k], u1[k]);
            ulonglong2 hA = *(const ulonglong2*)&h_sh[k][0];   // (h0,h1),(h2,h3)
            ulonglong2 hB = *(const ulonglong2*)&h_sh[k][4];   // (h4,h5),(h6,h7)
            a0[0] = fma2(hA.x, uk0, a0[0]);
            a0[1] = fma2(hA.y, uk0, a0[1]);
            a0[2] = fma2(hB.x, uk0, a0[2]);
            a0[3] = fma2(hB.y, uk0, a0[3]);
            a1[0] = fma2(hA.x, uk1, a1[0]);
            a1[1] = fma2(hA.y, uk1, a1[1]);
            a1[2] = fma2(hB.x, uk1, a1[2]);
            a1[3] = fma2(hB.y, uk1, a1[3]);
        }
#pragma unroll
        for (int p = 0; p < 4; p++) {
            z2[p][j]  = a0[p];
            z2[p][j2] = a1[p];
        }
        __syncthreads();

        // epilogue: 4 tasks per thread; tb = tbA + 2*s, lohi = tbA
        const float* zf_base = (const float*)z2;
#pragma unroll
        for (int s = 0; s < 4; s++) {
            int tb = tbA + 2 * s;
            // float index into z2 viewed flat: p*NG*2 + col*2 + (tb&1)
            int base = s * (NG * 2) + tbA;
            float zi = zf_base[base + (jc)       * 2];
            float zf = zf_base[base + (jc + 64)  * 2];
            float zg = zf_base[base + (jc + 128) * 2];
            float zo = zf_base[base + (jc + 192) * 2];
            float ig = sig_ap(zi);
            float fg = sig_ap(zf);
            float gg = (ACT == 0) ? tanh_ap(zg) : sig_ap(zg);
            float og = sig_ap(zo);
            c[s] = fmaf(fg, c[s], ig * gg);
            float ca = (ACT == 0) ? tanh_ap(c[s]) : sig_ap(c[s]);
            float h = og * ca;
            h_sh[jc][tb] = h;
            hout[((size_t)(b0 + tb) * TSEQ + t) * HU + jc] = h;
        }
        __syncthreads();
    }
}

// ---------------------------------------------------------------------------
// Launch
// ---------------------------------------------------------------------------
extern "C" void kernel_launch(void* const* d_in, const int* in_sizes, int n_in,
                              void* d_out, int out_size)
{
    const float* x  = (const float*)d_in[0];
    const float* W1 = (const float*)d_in[1];
    const float* U1 = (const float*)d_in[2];
    const float* b1 = (const float*)d_in[3];
    const float* W2 = (const float*)d_in[4];
    const float* U2 = (const float*)d_in[5];
    const float* b2 = (const float*)d_in[6];
    float* out = (float*)d_out;

    void *xz_p = nullptr, *h1_p = nullptr;
    cudaGetSymbolAddress(&xz_p, g_xz);
    cudaGetSymbolAddress(&h1_p, g_h1);
    float* xz = (float*)xz_p;
    float* h1 = (float*)h1_p;

    dim3 ggrid(MTOT / 128, 2);

    // Layer 1
    gemm_bias_kernel<128><<<ggrid, 256>>>(x, W1, b1, xz);
    lstm_rec_kernel<0><<<BATCH / 8, 128>>>(xz, U1, h1);

    // Layer 2 (input = h1, K=64)
    gemm_bias_kernel<64><<<ggrid, 256>>>(h1, W2, b2, xz);
    lstm_rec_kernel<1><<<BATCH / 8, 128>>>(xz, U2, out);
}

// round 8
// speedup vs baseline: 2.2687x; 1.3625x over previous
#include <cuda_runtime.h>
#include <cuda_bf16.h>
#include <math.h>

// Problem constants
#define TSEQ 128
#define HU   64
#define NG   256
#define BATCH 2048
#define MTOT (BATCH*TSEQ)

typedef unsigned long long u64;
typedef unsigned int u32;

// Scratch (__device__ globals)
__device__ float g_xz[(size_t)MTOT * NG];   // xz buffer (reused by both layers)
__device__ float g_h1[(size_t)MTOT * HU];   // layer-1 hidden sequence

// ---------------------------------------------------------------------------
// f32x2 packed-FMA + activation helpers (rec kernel)
// ---------------------------------------------------------------------------
__device__ __forceinline__ u64 pack2(float lo, float hi) {
    u64 r; asm("mov.b64 %0, {%1, %2};" : "=l"(r) : "f"(lo), "f"(hi)); return r;
}
__device__ __forceinline__ void unpack2(u64 v, float& lo, float& hi) {
    asm("mov.b64 {%0, %1}, %2;" : "=f"(lo), "=f"(hi) : "l"(v));
}
__device__ __forceinline__ u64 fma2(u64 a, u64 b, u64 c) {
    u64 r; asm("fma.rn.f32x2 %0, %1, %2, %3;" : "=l"(r) : "l"(a), "l"(b), "l"(c));
    return r;
}
__device__ __forceinline__ float tanh_ap(float x) {
    float y; asm("tanh.approx.f32 %0, %1;" : "=f"(y) : "f"(x)); return y;
}
__device__ __forceinline__ float sig_ap(float x) {
    return fmaf(0.5f, tanh_ap(0.5f * x), 0.5f);
}

// ---------------------------------------------------------------------------
// mma.sync / ldmatrix helpers (baseline PTX ISA — valid on plain sm_103)
// ---------------------------------------------------------------------------
__device__ __forceinline__ u32 smem_u32(const void* p) {
    u32 a;
    asm("{ .reg .u64 t; cvta.to.shared.u64 t, %1; cvt.u32.u64 %0, t; }"
        : "=r"(a) : "l"(p));
    return a;
}
__device__ __forceinline__ void ldsm4(u32 r[4], u32 addr) {
    asm volatile("ldmatrix.sync.aligned.m8n8.x4.shared.b16 {%0,%1,%2,%3}, [%4];"
                 : "=r"(r[0]), "=r"(r[1]), "=r"(r[2]), "=r"(r[3]) : "r"(addr));
}
__device__ __forceinline__ void ldsm4t(u32 r[4], u32 addr) {
    asm volatile("ldmatrix.sync.aligned.m8n8.x4.trans.shared.b16 {%0,%1,%2,%3}, [%4];"
                 : "=r"(r[0]), "=r"(r[1]), "=r"(r[2]), "=r"(r[3]) : "r"(addr));
}
__device__ __forceinline__ void mma16816(float d[4], const u32 a[4], const u32 b[2]) {
    asm volatile(
        "mma.sync.aligned.m16n8k16.row.col.f32.bf16.bf16.f32 "
        "{%0,%1,%2,%3}, {%4,%5,%6,%7}, {%8,%9}, {%0,%1,%2,%3};"
        : "+f"(d[0]), "+f"(d[1]), "+f"(d[2]), "+f"(d[3])
        : "r"(a[0]), "r"(a[1]), "r"(a[2]), "r"(a[3]), "r"(b[0]), "r"(b[1]));
}
// pack two fp32 -> bf16x2 (lo arg in lower half)
__device__ __forceinline__ u32 cvt2bf(float lo, float hi) {
    u32 r; asm("cvt.rn.bf16x2.f32 %0, %1, %2;" : "=r"(r) : "f"(hi), "f"(lo));
    return r;
}

// ---------------------------------------------------------------------------
// Tensor-core GEMM (HMMA): C[M,256] = A[M,KF32] @ W[KF32,256] + bias
// Split-fp32: D = a_hi*b_hi + a_lo*b_hi + a_hi*b_lo  (bf16 operands, fp32 acc)
// CTA: 128 rows x 256 cols, 256 threads (8 warps: 2M x 4N), warp tile 64x64.
// K chunked by 64.  SMEM:
//   As hi/lo: [128][64] bf16, row pitch 144 B (pad -> conflict-free ldmatrix)
//   Bs hi/lo: [64][256] bf16 (= W slice, n contiguous), row pitch 528 B
// A frags: ldmatrix.x4 (row-major);  B frags: ldmatrix.x4.trans.
// ---------------------------------------------------------------------------
#define A_PITCH 144
#define B_PITCH 528
#define S_AHI 0
#define S_ALO (128 * A_PITCH)                 // 18432
#define S_BHI (2 * 128 * A_PITCH)             // 36864
#define S_BLO (2 * 128 * A_PITCH + 64 * B_PITCH)   // 70656
#define GEMM_SMEM (2 * 128 * A_PITCH + 2 * 64 * B_PITCH)  // 104448

template <int KF32>
__global__ __launch_bounds__(256, 1) void gemm_tc_kernel(
    const float* __restrict__ A, const float* __restrict__ W,
    const float* __restrict__ bias, float* __restrict__ C)
{
    extern __shared__ char smem[];
    const u32 sb = smem_u32(smem);

    const int tid = threadIdx.x;
    const int wid = tid >> 5;
    const int l   = tid & 31;
    const int m0  = blockIdx.x * 128;
    const int wm  = (wid >> 2) * 64;     // warp M offset (0 / 64)
    const int wn  = (wid & 3) * 64;      // warp N offset

    float acc[128];
#pragma unroll
    for (int i = 0; i < 128; i++) acc[i] = 0.f;

    // ldmatrix per-thread base offsets (bytes)
    const u32 aoff = (u32)((wm + (l & 7) + ((l >> 3) & 1) * 8) * A_PITCH + (l >> 4) * 16);
    const u32 boff = (u32)(((l & 7) + ((l >> 3) & 1) * 8) * B_PITCH + (wn + (l >> 4) * 8) * 2);

    const int NCHUNK = KF32 / 64;
    for (int kc = 0; kc < NCHUNK; kc++) {
        const int k0 = kc * 64;

        // ---- stage A chunk: [128][64] fp32 -> hi/lo bf16 ----
        const float* Ab = A + (size_t)m0 * KF32 + k0;
#pragma unroll
        for (int i = 0; i < 8; i++) {
            int idx = tid + i * 256;          // 0..2047
            int m = idx >> 4, kq = idx & 15;  // k = kq*4
            float4 v = *(const float4*)(Ab + (size_t)m * KF32 + kq * 4);
            __nv_bfloat16 h0 = __float2bfloat16(v.x);
            __nv_bfloat16 h1 = __float2bfloat16(v.y);
            __nv_bfloat16 h2 = __float2bfloat16(v.z);
            __nv_bfloat16 h3 = __float2bfloat16(v.w);
            u32 hp0 = ((u32)__bfloat16_as_ushort(h1) << 16) | __bfloat16_as_ushort(h0);
            u32 hp1 = ((u32)__bfloat16_as_ushort(h3) << 16) | __bfloat16_as_ushort(h2);
            u32 lp0 = cvt2bf(v.x - __bfloat162float(h0), v.y - __bfloat162float(h1));
            u32 lp1 = cvt2bf(v.z - __bfloat162float(h2), v.w - __bfloat162float(h3));
            u32 off = (u32)(m * A_PITCH + kq * 8);
            *(u64*)(smem + S_AHI + off) = ((u64)hp1 << 32) | hp0;
            *(u64*)(smem + S_ALO + off) = ((u64)lp1 << 32) | lp0;
        }
        // ---- stage B chunk: W[k0+k][n], [64][256] fp32 -> hi/lo bf16 ----
        const float* Wb = W + (size_t)k0 * NG;
#pragma unroll
        for (int i = 0; i < 16; i++) {
            int idx = tid + i * 256;          // 0..4095
            int k = idx >> 6, nq = idx & 63;  // n = nq*4
            float4 v = *(const float4*)(Wb + (size_t)k * NG + nq * 4);
            __nv_bfloat16 h0 = __float2bfloat16(v.x);
            __nv_bfloat16 h1 = __float2bfloat16(v.y);
            __nv_bfloat16 h2 = __float2bfloat16(v.z);
            __nv_bfloat16 h3 = __float2bfloat16(v.w);
            u32 hp0 = ((u32)__bfloat16_as_ushort(h1) << 16) | __bfloat16_as_ushort(h0);
            u32 hp1 = ((u32)__bfloat16_as_ushort(h3) << 16) | __bfloat16_as_ushort(h2);
            u32 lp0 = cvt2bf(v.x - __bfloat162float(h0), v.y - __bfloat162float(h1));
            u32 lp1 = cvt2bf(v.z - __bfloat162float(h2), v.w - __bfloat162float(h3));
            u32 off = (u32)(k * B_PITCH + nq * 8);
            *(u64*)(smem + S_BHI + off) = ((u64)hp1 << 32) | hp0;
            *(u64*)(smem + S_BLO + off) = ((u64)lp1 << 32) | lp0;
        }
        __syncthreads();

        // ---- MMA over 4 k16 steps ----
#pragma unroll
        for (int ks = 0; ks < 4; ks++) {
            u32 ahi[4][4], alo[4][4];
#pragma unroll
            for (int mt = 0; mt < 4; mt++) {
                u32 ao = aoff + (u32)(mt * 16 * A_PITCH + ks * 32);
                ldsm4(ahi[mt], sb + S_AHI + ao);
                ldsm4(alo[mt], sb + S_ALO + ao);
            }
#pragma unroll
            for (int ntp = 0; ntp < 4; ntp++) {
                u32 bo = boff + (u32)(ks * 16 * B_PITCH + ntp * 32);
                u32 bhi[4], blo[4];
                ldsm4t(bhi, sb + S_BHI + bo);
                ldsm4t(blo, sb + S_BLO + bo);
#pragma unroll
                for (int mt = 0; mt < 4; mt++) {
#pragma unroll
                    for (int h = 0; h < 2; h++) {
                        int nt = ntp * 2 + h;
                        float* d = &acc[(mt * 8 + nt) * 4];
                        mma16816(d, ahi[mt], &bhi[h * 2]);
                        mma16816(d, alo[mt], &bhi[h * 2]);
                        mma16816(d, ahi[mt], &blo[h * 2]);
                    }
                }
            }
        }
        __syncthreads();
    }

    // ---- epilogue: bias + store ----
#pragma unroll
    for (int mt = 0; mt < 4; mt++) {
        int r0 = m0 + wm + mt * 16 + (l >> 2);
#pragma unroll
        for (int nt = 0; nt < 8; nt++) {
            int col = wn + nt * 8 + 2 * (l & 3);
            float2 bv = *(const float2*)(bias + col);
            const float* d = &acc[(mt * 8 + nt) * 4];
            float2 o0 = make_float2(d[0] + bv.x, d[1] + bv.y);
            float2 o1 = make_float2(d[2] + bv.x, d[3] + bv.y);
            *(float2*)(C + (size_t)r0 * NG + col)       = o0;
            *(float2*)(C + (size_t)(r0 + 8) * NG + col) = o1;
        }
    }
}

// ---------------------------------------------------------------------------
// Recurrent kernel (unchanged from R4: 265 us/layer).
// ---------------------------------------------------------------------------
template <int ACT>
__global__ __launch_bounds__(128) void lstm_rec_kernel(
    const float* __restrict__ xz, const float* __restrict__ U,
    float* __restrict__ hout)
{
    const int TB = 8;
    __shared__ __align__(16) float h_sh[HU][TB];
    __shared__ __align__(16) u64 z2[4][NG];

    const int j  = threadIdx.x;
    const int j2 = j + 128;
    const int b0 = blockIdx.x * TB;

    float u0[HU], u1[HU];
#pragma unroll
    for (int k = 0; k < HU; k++) {
        u0[k] = U[(size_t)k * NG + j];
        u1[k] = U[(size_t)k * NG + j2];
    }

    if (j < HU * TB / 4) ((float4*)h_sh)[j] = make_float4(0.f, 0.f, 0.f, 0.f);

    const int jc  = j & 63;
    const int tbA = j >> 6;
    float c[4] = {0.f, 0.f, 0.f, 0.f};

    const float* xb = xz + (size_t)b0 * TSEQ * NG;

    float xn0[TB], xn1[TB];
#pragma unroll
    for (int tb = 0; tb < TB; tb++) {
        xn0[tb] = xb[(size_t)(tb * TSEQ) * NG + j];
        xn1[tb] = xb[(size_t)(tb * TSEQ) * NG + j2];
    }

    __syncthreads();

    for (int t = 0; t < TSEQ; t++) {
        u64 a0[4], a1[4];
#pragma unroll
        for (int p = 0; p < 4; p++) {
            a0[p] = pack2(xn0[2 * p], xn0[2 * p + 1]);
            a1[p] = pack2(xn1[2 * p], xn1[2 * p + 1]);
        }
        if (t + 1 < TSEQ) {
#pragma unroll
            for (int tb = 0; tb < TB; tb++) {
                xn0[tb] = xb[(size_t)(tb * TSEQ + t + 1) * NG + j];
                xn1[tb] = xb[(size_t)(tb * TSEQ + t + 1) * NG + j2];
            }
        }

#pragma unroll
        for (int k = 0; k < HU; k++) {
            u64 uk0 = pack2(u0[k], u0[k]);
            u64 uk1 = pack2(u1[k], u1[k]);
            ulonglong2 hA = *(const ulonglong2*)&h_sh[k][0];
            ulonglong2 hB = *(const ulonglong2*)&h_sh[k][4];
            a0[0] = fma2(hA.x, uk0, a0[0]);
            a0[1] = fma2(hA.y, uk0, a0[1]);
            a0[2] = fma2(hB.x, uk0, a0[2]);
            a0[3] = fma2(hB.y, uk0, a0[3]);
            a1[0] = fma2(hA.x, uk1, a1[0]);
            a1[1] = fma2(hA.y, uk1, a1[1]);
            a1[2] = fma2(hB.x, uk1, a1[2]);
            a1[3] = fma2(hB.y, uk1, a1[3]);
        }
#pragma unroll
        for (int p = 0; p < 4; p++) {
            z2[p][j]  = a0[p];
            z2[p][j2] = a1[p];
        }
        __syncthreads();

        const float* zf_base = (const float*)z2;
#pragma unroll
        for (int s = 0; s < 4; s++) {
            int tb = tbA + 2 * s;
            int base = s * (NG * 2) + tbA;
            float zi = zf_base[base + (jc)       * 2];
            float zf = zf_base[base + (jc + 64)  * 2];
            float zg = zf_base[base + (jc + 128) * 2];
            float zo = zf_base[base + (jc + 192) * 2];
            float ig = sig_ap(zi);
            float fg = sig_ap(zf);
            float gg = (ACT == 0) ? tanh_ap(zg) : sig_ap(zg);
            float og = sig_ap(zo);
            c[s] = fmaf(fg, c[s], ig * gg);
            float ca = (ACT == 0) ? tanh_ap(c[s]) : sig_ap(c[s]);
            float h = og * ca;
            h_sh[jc][tb] = h;
            hout[((size_t)(b0 + tb) * TSEQ + t) * HU + jc] = h;
        }
        __syncthreads();
    }
}

// ---------------------------------------------------------------------------
// Launch
// ---------------------------------------------------------------------------
extern "C" void kernel_launch(void* const* d_in, const int* in_sizes, int n_in,
                              void* d_out, int out_size)
{
    const float* x  = (const float*)d_in[0];
    const float* W1 = (const float*)d_in[1];
    const float* U1 = (const float*)d_in[2];
    const float* b1 = (const float*)d_in[3];
    const float* W2 = (const float*)d_in[4];
    const float* U2 = (const float*)d_in[5];
    const float* b2 = (const float*)d_in[6];
    float* out = (float*)d_out;

    void *xz_p = nullptr, *h1_p = nullptr;
    cudaGetSymbolAddress(&xz_p, g_xz);
    cudaGetSymbolAddress(&h1_p, g_h1);
    float* xz = (float*)xz_p;
    float* h1 = (float*)h1_p;

    cudaFuncSetAttribute(gemm_tc_kernel<128>,
                         cudaFuncAttributeMaxDynamicSharedMemorySize, GEMM_SMEM);
    cudaFuncSetAttribute(gemm_tc_kernel<64>,
                         cudaFuncAttributeMaxDynamicSharedMemorySize, GEMM_SMEM);

    // Layer 1
    gemm_tc_kernel<128><<<MTOT / 128, 256, GEMM_SMEM>>>(x, W1, b1, xz);
    lstm_rec_kernel<0><<<BATCH / 8, 128>>>(xz, U1, h1);

    // Layer 2 (input = h1, K=64)
    gemm_tc_kernel<64><<<MTOT / 128, 256, GEMM_SMEM>>>(h1, W2, b2, xz);
    lstm_rec_kernel<1><<<BATCH / 8, 128>>>(xz, U2, out);
}

// round 9
// speedup vs baseline: 2.4368x; 1.0741x over previous
#include <cuda_runtime.h>
#include <cuda_bf16.h>
#include <math.h>

// Problem constants
#define TSEQ 128
#define HU   64
#define NG   256
#define BATCH 2048
#define MTOT (BATCH*TSEQ)

typedef unsigned long long u64;
typedef unsigned int u32;

// Scratch (__device__ globals)
__device__ float g_xz[(size_t)MTOT * NG];   // xz buffer (reused by both layers)
__device__ float g_h1[(size_t)MTOT * HU];   // layer-1 hidden sequence

// ---------------------------------------------------------------------------
// Activation helpers
// ---------------------------------------------------------------------------
__device__ __forceinline__ float tanh_ap(float x) {
    float y; asm("tanh.approx.f32 %0, %1;" : "=f"(y) : "f"(x)); return y;
}
__device__ __forceinline__ float sig_ap(float x) {
    return fmaf(0.5f, tanh_ap(0.5f * x), 0.5f);
}

// ---------------------------------------------------------------------------
// mma.sync / ldmatrix helpers (baseline PTX ISA — valid on plain sm_103)
// ---------------------------------------------------------------------------
__device__ __forceinline__ u32 smem_u32(const void* p) {
    u32 a;
    asm("{ .reg .u64 t; cvta.to.shared.u64 t, %1; cvt.u32.u64 %0, t; }"
        : "=r"(a) : "l"(p));
    return a;
}
__device__ __forceinline__ void ldsm4(u32 r[4], u32 addr) {
    asm volatile("ldmatrix.sync.aligned.m8n8.x4.shared.b16 {%0,%1,%2,%3}, [%4];"
                 : "=r"(r[0]), "=r"(r[1]), "=r"(r[2]), "=r"(r[3]) : "r"(addr));
}
__device__ __forceinline__ void ldsm4t(u32 r[4], u32 addr) {
    asm volatile("ldmatrix.sync.aligned.m8n8.x4.trans.shared.b16 {%0,%1,%2,%3}, [%4];"
                 : "=r"(r[0]), "=r"(r[1]), "=r"(r[2]), "=r"(r[3]) : "r"(addr));
}
__device__ __forceinline__ void mma16816(float d[4], const u32 a[4], const u32 b[2]) {
    asm volatile(
        "mma.sync.aligned.m16n8k16.row.col.f32.bf16.bf16.f32 "
        "{%0,%1,%2,%3}, {%4,%5,%6,%7}, {%8,%9}, {%0,%1,%2,%3};"
        : "+f"(d[0]), "+f"(d[1]), "+f"(d[2]), "+f"(d[3])
        : "r"(a[0]), "r"(a[1]), "r"(a[2]), "r"(a[3]), "r"(b[0]), "r"(b[1]));
}
// pack two fp32 -> bf16x2 (first arg in lower half)
__device__ __forceinline__ u32 cvt2bf(float lo, float hi) {
    u32 r; asm("cvt.rn.bf16x2.f32 %0, %1, %2;" : "=r"(r) : "f"(hi), "f"(lo));
    return r;
}

// ---------------------------------------------------------------------------
// Tensor-core GEMM (HMMA): C[M,256] = A[M,KF32] @ W[KF32,256] + bias
// (unchanged from R8: passing at rel_err 1.3e-6)
// ---------------------------------------------------------------------------
#define A_PITCH 144
#define B_PITCH 528
#define S_AHI 0
#define S_ALO (128 * A_PITCH)
#define S_BHI (2 * 128 * A_PITCH)
#define S_BLO (2 * 128 * A_PITCH + 64 * B_PITCH)
#define GEMM_SMEM (2 * 128 * A_PITCH + 2 * 64 * B_PITCH)  // 104448

template <int KF32>
__global__ __launch_bounds__(256, 1) void gemm_tc_kernel(
    const float* __restrict__ A, const float* __restrict__ W,
    const float* __restrict__ bias, float* __restrict__ C)
{
    extern __shared__ char smem[];
    const u32 sb = smem_u32(smem);

    const int tid = threadIdx.x;
    const int wid = tid >> 5;
    const int l   = tid & 31;
    const int m0  = blockIdx.x * 128;
    const int wm  = (wid >> 2) * 64;
    const int wn  = (wid & 3) * 64;

    float acc[128];
#pragma unroll
    for (int i = 0; i < 128; i++) acc[i] = 0.f;

    const u32 aoff = (u32)((wm + (l & 7) + ((l >> 3) & 1) * 8) * A_PITCH + (l >> 4) * 16);
    const u32 boff = (u32)(((l & 7) + ((l >> 3) & 1) * 8) * B_PITCH + (wn + (l >> 4) * 8) * 2);

    const int NCHUNK = KF32 / 64;
    for (int kc = 0; kc < NCHUNK; kc++) {
        const int k0 = kc * 64;

        const float* Ab = A + (size_t)m0 * KF32 + k0;
#pragma unroll
        for (int i = 0; i < 8; i++) {
            int idx = tid + i * 256;
            int m = idx >> 4, kq = idx & 15;
            float4 v = *(const float4*)(Ab + (size_t)m * KF32 + kq * 4);
            __nv_bfloat16 h0 = __float2bfloat16(v.x);
            __nv_bfloat16 h1 = __float2bfloat16(v.y);
            __nv_bfloat16 h2 = __float2bfloat16(v.z);
            __nv_bfloat16 h3 = __float2bfloat16(v.w);
            u32 hp0 = ((u32)__bfloat16_as_ushort(h1) << 16) | __bfloat16_as_ushort(h0);
            u32 hp1 = ((u32)__bfloat16_as_ushort(h3) << 16) | __bfloat16_as_ushort(h2);
            u32 lp0 = cvt2bf(v.x - __bfloat162float(h0), v.y - __bfloat162float(h1));
            u32 lp1 = cvt2bf(v.z - __bfloat162float(h2), v.w - __bfloat162float(h3));
            u32 off = (u32)(m * A_PITCH + kq * 8);
            *(u64*)(smem + S_AHI + off) = ((u64)hp1 << 32) | hp0;
            *(u64*)(smem + S_ALO + off) = ((u64)lp1 << 32) | lp0;
        }
        const float* Wb = W + (size_t)k0 * NG;
#pragma unroll
        for (int i = 0; i < 16; i++) {
            int idx = tid + i * 256;
            int k = idx >> 6, nq = idx & 63;
            float4 v = *(const float4*)(Wb + (size_t)k * NG + nq * 4);
            __nv_bfloat16 h0 = __float2bfloat16(v.x);
            __nv_bfloat16 h1 = __float2bfloat16(v.y);
            __nv_bfloat16 h2 = __float2bfloat16(v.z);
            __nv_bfloat16 h3 = __float2bfloat16(v.w);
            u32 hp0 = ((u32)__bfloat16_as_ushort(h1) << 16) | __bfloat16_as_ushort(h0);
            u32 hp1 = ((u32)__bfloat16_as_ushort(h3) << 16) | __bfloat16_as_ushort(h2);
            u32 lp0 = cvt2bf(v.x - __bfloat162float(h0), v.y - __bfloat162float(h1));
            u32 lp1 = cvt2bf(v.z - __bfloat162float(h2), v.w - __bfloat162float(h3));
            u32 off = (u32)(k * B_PITCH + nq * 8);
            *(u64*)(smem + S_BHI + off) = ((u64)hp1 << 32) | hp0;
            *(u64*)(smem + S_BLO + off) = ((u64)lp1 << 32) | lp0;
        }
        __syncthreads();

#pragma unroll
        for (int ks = 0; ks < 4; ks++) {
            u32 ahi[4][4], alo[4][4];
#pragma unroll
            for (int mt = 0; mt < 4; mt++) {
                u32 ao = aoff + (u32)(mt * 16 * A_PITCH + ks * 32);
                ldsm4(ahi[mt], sb + S_AHI + ao);
                ldsm4(alo[mt], sb + S_ALO + ao);
            }
#pragma unroll
            for (int ntp = 0; ntp < 4; ntp++) {
                u32 bo = boff + (u32)(ks * 16 * B_PITCH + ntp * 32);
                u32 bhi[4], blo[4];
                ldsm4t(bhi, sb + S_BHI + bo);
                ldsm4t(blo, sb + S_BLO + bo);
#pragma unroll
                for (int mt = 0; mt < 4; mt++) {
#pragma unroll
                    for (int h = 0; h < 2; h++) {
                        int nt = ntp * 2 + h;
                        float* d = &acc[(mt * 8 + nt) * 4];
                        mma16816(d, ahi[mt], &bhi[h * 2]);
                        mma16816(d, alo[mt], &bhi[h * 2]);
                        mma16816(d, ahi[mt], &blo[h * 2]);
                    }
                }
            }
        }
        __syncthreads();
    }

#pragma unroll
    for (int mt = 0; mt < 4; mt++) {
        int r0 = m0 + wm + mt * 16 + (l >> 2);
#pragma unroll
        for (int nt = 0; nt < 8; nt++) {
            int col = wn + nt * 8 + 2 * (l & 3);
            float2 bv = *(const float2*)(bias + col);
            const float* d = &acc[(mt * 8 + nt) * 4];
            float2 o0 = make_float2(d[0] + bv.x, d[1] + bv.y);
            float2 o1 = make_float2(d[2] + bv.x, d[3] + bv.y);
            *(float2*)(C + (size_t)r0 * NG + col)       = o0;
            *(float2*)(C + (size_t)(r0 + 8) * NG + col) = o1;
        }
    }
}

// ---------------------------------------------------------------------------
// Tensor-core recurrent kernel.
// 128 blocks x TB=16 batch rows, 128 threads (4 warps).
// Warp w owns gate columns {16w..16w+15} + 64g (g = gate 0..3) — column-
// interleaved so every thread holds zi/zf/zg/zo for the same (row, unit)
// in registers after the MMAs.
// U: staged once to smem (hi/lo bf16, pitch 528), B-fragments preloaded to
// registers before the t-loop (128 regs), never touched again.
// Per step: acc := xz fragments (prefetched), 8 ldmatrix + 96 mma.sync
// (3-term split-fp32), in-register gates, h -> bf16 hi/lo double-buffered
// smem + fp32 gmem. 1 barrier/step.
// ---------------------------------------------------------------------------
#define RS_UHI 0
#define RS_ULO 33792                 // 64*528
#define RS_H   67584                 // 2 bufs x 2 terms x [16][144]
#define REC_SMEM (67584 + 9216)      // 76800

template <int ACT>
__global__ __launch_bounds__(128, 1) void lstm_rec_mma(
    const float* __restrict__ xz, const float* __restrict__ U,
    float* __restrict__ hout)
{
    extern __shared__ char smem[];
    const u32 sb = smem_u32(smem);

    const int tid = threadIdx.x;
    const int w   = tid >> 5;
    const int l   = tid & 31;
    const int b0  = blockIdx.x * 16;

    // ---- stage U (64x256 fp32) -> hi/lo bf16, pitch 528 ----
#pragma unroll
    for (int i = 0; i < 32; i++) {
        int idx = tid + i * 128;          // 0..4095
        int k = idx >> 6, nq = idx & 63;
        float4 v = *(const float4*)(U + (size_t)k * NG + nq * 4);
        __nv_bfloat16 h0 = __float2bfloat16(v.x);
        __nv_bfloat16 h1 = __float2bfloat16(v.y);
        __nv_bfloat16 h2 = __float2bfloat16(v.z);
        __nv_bfloat16 h3 = __float2bfloat16(v.w);
        u32 hp0 = ((u32)__bfloat16_as_ushort(h1) << 16) | __bfloat16_as_ushort(h0);
        u32 hp1 = ((u32)__bfloat16_as_ushort(h3) << 16) | __bfloat16_as_ushort(h2);
        u32 lp0 = cvt2bf(v.x - __bfloat162float(h0), v.y - __bfloat162float(h1));
        u32 lp1 = cvt2bf(v.z - __bfloat162float(h2), v.w - __bfloat162float(h3));
        u32 off = (u32)(k * B_PITCH + nq * 8);
        *(u64*)(smem + RS_UHI + off) = ((u64)hp1 << 32) | hp0;
        *(u64*)(smem + RS_ULO + off) = ((u64)lp1 << 32) | lp0;
    }
    // zero both h buffers (2304 u32)
#pragma unroll
    for (int i = 0; i < 18; i++)
        ((u32*)(smem + RS_H))[tid + i * 128] = 0;
    __syncthreads();

    // ---- preload B-fragments (U) into registers ----
    u32 bh[4][4][4], bl[4][4][4];    // [gate][kstep][4 regs = 2 n-tiles]
    {
        const u32 brow = (u32)((l & 7) + ((l >> 3) & 1) * 8);
        const u32 bcol = (u32)((l >> 4) * 16);
#pragma unroll
        for (int g = 0; g < 4; g++)
#pragma unroll
            for (int ks = 0; ks < 4; ks++) {
                u32 off = (ks * 16 + brow) * B_PITCH + (u32)(64 * g + 16 * w) * 2 + bcol;
                ldsm4t(bh[g][ks], sb + RS_UHI + off);
                ldsm4t(bl[g][ks], sb + RS_ULO + off);
            }
    }

    // per-thread output ownership
    const int r   = l >> 2;               // rows r and r+8 (within 16)
    const int cq  = 2 * (l & 3);          // col pair base within 8-col tile
    float c[8];
#pragma unroll
    for (int i = 0; i < 8; i++) c[i] = 0.f;

    // xz row base pointers
    const float* pA = xz + (size_t)(b0 + r)     * TSEQ * NG;
    const float* pB = xz + (size_t)(b0 + r + 8) * TSEQ * NG;

    // prefetch xz for t=0
    float xn[32];
#pragma unroll
    for (int g = 0; g < 4; g++)
#pragma unroll
        for (int h = 0; h < 2; h++) {
            int col = 64 * g + 16 * w + 8 * h + cq;
            float2 vA = *(const float2*)(pA + col);
            float2 vB = *(const float2*)(pB + col);
            int base = (g * 2 + h) * 4;
            xn[base + 0] = vA.x; xn[base + 1] = vA.y;
            xn[base + 2] = vB.x; xn[base + 3] = vB.y;
        }

    const u32 aoffb = (u32)(((l & 7) + ((l >> 3) & 1) * 8) * A_PITCH + (l >> 4) * 16);
    int buf = 0;
    __syncthreads();

    for (int t = 0; t < TSEQ; t++) {
        // acc := xz fragments
        float acc[32];
#pragma unroll
        for (int i = 0; i < 32; i++) acc[i] = xn[i];
        // prefetch next step
        if (t + 1 < TSEQ) {
#pragma unroll
            for (int g = 0; g < 4; g++)
#pragma unroll
                for (int h = 0; h < 2; h++) {
                    int col = 64 * g + 16 * w + 8 * h + cq;
                    float2 vA = *(const float2*)(pA + (size_t)(t + 1) * NG + col);
                    float2 vB = *(const float2*)(pB + (size_t)(t + 1) * NG + col);
                    int base = (g * 2 + h) * 4;
                    xn[base + 0] = vA.x; xn[base + 1] = vA.y;
                    xn[base + 2] = vB.x; xn[base + 3] = vB.y;
                }
        }

        // ---- MMAs: z += h_prev @ U ----
        const u32 hbase = sb + RS_H + (u32)(buf * 4608);
#pragma unroll
        for (int ks = 0; ks < 4; ks++) {
            u32 ah[4], al[4];
            ldsm4(ah, hbase + aoffb + ks * 32);
            ldsm4(al, hbase + 2304 + aoffb + ks * 32);
#pragma unroll
            for (int g = 0; g < 4; g++)
#pragma unroll
                for (int h = 0; h < 2; h++) {
                    float* d = &acc[(g * 2 + h) * 4];
                    mma16816(d, ah, &bh[g][ks][h * 2]);
                    mma16816(d, al, &bh[g][ks][h * 2]);
                    mma16816(d, ah, &bl[g][ks][h * 2]);
                }
        }

        // ---- gates (all in registers) + h writeback ----
        const u32 nbase = sb + RS_H + (u32)((buf ^ 1) * 4608);
#pragma unroll
        for (int h = 0; h < 2; h++) {
#pragma unroll
            for (int r01 = 0; r01 < 2; r01++) {
                float hv[2];
#pragma unroll
                for (int e = 0; e < 2; e++) {
                    int fi = r01 * 2 + e;
                    float zi = acc[(0 * 2 + h) * 4 + fi];
                    float zf = acc[(1 * 2 + h) * 4 + fi];
                    float zg = acc[(2 * 2 + h) * 4 + fi];
                    float zo = acc[(3 * 2 + h) * 4 + fi];
                    float ig = sig_ap(zi);
                    float fg = sig_ap(zf);
                    float gg = (ACT == 0) ? tanh_ap(zg) : sig_ap(zg);
                    float og = sig_ap(zo);
                    int ci = h * 4 + r01 * 2 + e;
                    c[ci] = fmaf(fg, c[ci], ig * gg);
                    float ca = (ACT == 0) ? tanh_ap(c[ci]) : sig_ap(c[ci]);
                    hv[e] = og * ca;
                }
                // pack hi/lo bf16 pairs, store to next h buffer
                __nv_bfloat16 b0h = __float2bfloat16(hv[0]);
                __nv_bfloat16 b1h = __float2bfloat16(hv[1]);
                u32 hip = ((u32)__bfloat16_as_ushort(b1h) << 16) | __bfloat16_as_ushort(b0h);
                u32 lop = cvt2bf(hv[0] - __bfloat162float(b0h),
                                 hv[1] - __bfloat162float(b1h));
                int row_s = r + 8 * r01;
                int u0 = 16 * w + 8 * h + cq;
                u32 hoff = (u32)(row_s * A_PITCH + u0 * 2);
                *(u32*)((char*)smem + (nbase - sb) + hoff)        = hip;
                *(u32*)((char*)smem + (nbase - sb) + 2304 + hoff) = lop;
                // fp32 to gmem
                *(float2*)(hout + ((size_t)(b0 + row_s) * TSEQ + t) * HU + u0) =
                    make_float2(hv[0], hv[1]);
            }
        }
        __syncthreads();
        buf ^= 1;
    }
}

// ---------------------------------------------------------------------------
// Launch
// ---------------------------------------------------------------------------
extern "C" void kernel_launch(void* const* d_in, const int* in_sizes, int n_in,
                              void* d_out, int out_size)
{
    const float* x  = (const float*)d_in[0];
    const float* W1 = (const float*)d_in[1];
    const float* U1 = (const float*)d_in[2];
    const float* b1 = (const float*)d_in[3];
    const float* W2 = (const float*)d_in[4];
    const float* U2 = (const float*)d_in[5];
    const float* b2 = (const float*)d_in[6];
    float* out = (float*)d_out;

    void *xz_p = nullptr, *h1_p = nullptr;
    cudaGetSymbolAddress(&xz_p, g_xz);
    cudaGetSymbolAddress(&h1_p, g_h1);
    float* xz = (float*)xz_p;
    float* h1 = (float*)h1_p;

    cudaFuncSetAttribute(gemm_tc_kernel<128>,
                         cudaFuncAttributeMaxDynamicSharedMemorySize, GEMM_SMEM);
    cudaFuncSetAttribute(gemm_tc_kernel<64>,
                         cudaFuncAttributeMaxDynamicSharedMemorySize, GEMM_SMEM);
    cudaFuncSetAttribute(lstm_rec_mma<0>,
                         cudaFuncAttributeMaxDynamicSharedMemorySize, REC_SMEM);
    cudaFuncSetAttribute(lstm_rec_mma<1>,
                         cudaFuncAttributeMaxDynamicSharedMemorySize, REC_SMEM);

    // Layer 1
    gemm_tc_kernel<128><<<MTOT / 128, 256, GEMM_SMEM>>>(x, W1, b1, xz);
    lstm_rec_mma<0><<<BATCH / 16, 128, REC_SMEM>>>(xz, U1, h1);

    // Layer 2 (input = h1, K=64)
    gemm_tc_kernel<64><<<MTOT / 128, 256, GEMM_SMEM>>>(h1, W2, b2, xz);
    lstm_rec_mma<1><<<BATCH / 16, 128, REC_SMEM>>>(xz, U2, out);
}

// round 10
// speedup vs baseline: 2.9407x; 1.2068x over previous
#include <cuda_runtime.h>
#include <cuda_bf16.h>
#include <math.h>

// Problem constants
#define TSEQ 128
#define HU   64
#define NG   256
#define BATCH 2048
#define MTOT (BATCH*TSEQ)

typedef unsigned long long u64;
typedef unsigned int u32;

// Scratch (__device__ globals)
__device__ float g_xz[(size_t)MTOT * NG];   // xz buffer (reused by both layers)
__device__ float g_h1[(size_t)MTOT * HU];   // layer-1 hidden sequence

// ---------------------------------------------------------------------------
// Activation helpers
// ---------------------------------------------------------------------------
__device__ __forceinline__ float tanh_ap(float x) {
    float y; asm("tanh.approx.f32 %0, %1;" : "=f"(y) : "f"(x)); return y;
}
__device__ __forceinline__ float sig_ap(float x) {
    return fmaf(0.5f, tanh_ap(0.5f * x), 0.5f);
}

// ---------------------------------------------------------------------------
// mma.sync / ldmatrix helpers (baseline PTX ISA — valid on plain sm_103)
// ---------------------------------------------------------------------------
__device__ __forceinline__ u32 smem_u32(const void* p) {
    u32 a;
    asm("{ .reg .u64 t; cvta.to.shared.u64 t, %1; cvt.u32.u64 %0, t; }"
        : "=r"(a) : "l"(p));
    return a;
}
__device__ __forceinline__ void ldsm4(u32 r[4], u32 addr) {
    asm volatile("ldmatrix.sync.aligned.m8n8.x4.shared.b16 {%0,%1,%2,%3}, [%4];"
                 : "=r"(r[0]), "=r"(r[1]), "=r"(r[2]), "=r"(r[3]) : "r"(addr));
}
__device__ __forceinline__ void ldsm4t(u32 r[4], u32 addr) {
    asm volatile("ldmatrix.sync.aligned.m8n8.x4.trans.shared.b16 {%0,%1,%2,%3}, [%4];"
                 : "=r"(r[0]), "=r"(r[1]), "=r"(r[2]), "=r"(r[3]) : "r"(addr));
}
__device__ __forceinline__ void ldsm2t(u32 r[2], u32 addr) {
    asm volatile("ldmatrix.sync.aligned.m8n8.x2.trans.shared.b16 {%0,%1}, [%2];"
                 : "=r"(r[0]), "=r"(r[1]) : "r"(addr));
}
__device__ __forceinline__ void mma16816(float d[4], const u32 a[4], const u32 b[2]) {
    asm volatile(
        "mma.sync.aligned.m16n8k16.row.col.f32.bf16.bf16.f32 "
        "{%0,%1,%2,%3}, {%4,%5,%6,%7}, {%8,%9}, {%0,%1,%2,%3};"
        : "+f"(d[0]), "+f"(d[1]), "+f"(d[2]), "+f"(d[3])
        : "r"(a[0]), "r"(a[1]), "r"(a[2]), "r"(a[3]), "r"(b[0]), "r"(b[1]));
}
// pack two fp32 -> bf16x2 (first arg in lower half)
__device__ __forceinline__ u32 cvt2bf(float lo, float hi) {
    u32 r; asm("cvt.rn.bf16x2.f32 %0, %1, %2;" : "=r"(r) : "f"(hi), "f"(lo));
    return r;
}

// ---------------------------------------------------------------------------
// Tensor-core GEMM (HMMA): C[M,256] = A[M,KF32] @ W[KF32,256] + bias
// (unchanged from R8: passing at rel_err 1.3e-6)
// ---------------------------------------------------------------------------
#define A_PITCH 144
#define B_PITCH 528
#define S_AHI 0
#define S_ALO (128 * A_PITCH)
#define S_BHI (2 * 128 * A_PITCH)
#define S_BLO (2 * 128 * A_PITCH + 64 * B_PITCH)
#define GEMM_SMEM (2 * 128 * A_PITCH + 2 * 64 * B_PITCH)  // 104448

template <int KF32>
__global__ __launch_bounds__(256, 1) void gemm_tc_kernel(
    const float* __restrict__ A, const float* __restrict__ W,
    const float* __restrict__ bias, float* __restrict__ C)
{
    extern __shared__ char smem[];
    const u32 sb = smem_u32(smem);

    const int tid = threadIdx.x;
    const int wid = tid >> 5;
    const int l   = tid & 31;
    const int m0  = blockIdx.x * 128;
    const int wm  = (wid >> 2) * 64;
    const int wn  = (wid & 3) * 64;

    float acc[128];
#pragma unroll
    for (int i = 0; i < 128; i++) acc[i] = 0.f;

    const u32 aoff = (u32)((wm + (l & 7) + ((l >> 3) & 1) * 8) * A_PITCH + (l >> 4) * 16);
    const u32 boff = (u32)(((l & 7) + ((l >> 3) & 1) * 8) * B_PITCH + (wn + (l >> 4) * 8) * 2);

    const int NCHUNK = KF32 / 64;
    for (int kc = 0; kc < NCHUNK; kc++) {
        const int k0 = kc * 64;

        const float* Ab = A + (size_t)m0 * KF32 + k0;
#pragma unroll
        for (int i = 0; i < 8; i++) {
            int idx = tid + i * 256;
            int m = idx >> 4, kq = idx & 15;
            float4 v = *(const float4*)(Ab + (size_t)m * KF32 + kq * 4);
            __nv_bfloat16 h0 = __float2bfloat16(v.x);
            __nv_bfloat16 h1 = __float2bfloat16(v.y);
            __nv_bfloat16 h2 = __float2bfloat16(v.z);
            __nv_bfloat16 h3 = __float2bfloat16(v.w);
            u32 hp0 = ((u32)__bfloat16_as_ushort(h1) << 16) | __bfloat16_as_ushort(h0);
            u32 hp1 = ((u32)__bfloat16_as_ushort(h3) << 16) | __bfloat16_as_ushort(h2);
            u32 lp0 = cvt2bf(v.x - __bfloat162float(h0), v.y - __bfloat162float(h1));
            u32 lp1 = cvt2bf(v.z - __bfloat162float(h2), v.w - __bfloat162float(h3));
            u32 off = (u32)(m * A_PITCH + kq * 8);
            *(u64*)(smem + S_AHI + off) = ((u64)hp1 << 32) | hp0;
            *(u64*)(smem + S_ALO + off) = ((u64)lp1 << 32) | lp0;
        }
        const float* Wb = W + (size_t)k0 * NG;
#pragma unroll
        for (int i = 0; i < 16; i++) {
            int idx = tid + i * 256;
            int k = idx >> 6, nq = idx & 63;
            float4 v = *(const float4*)(Wb + (size_t)k * NG + nq * 4);
            __nv_bfloat16 h0 = __float2bfloat16(v.x);
            __nv_bfloat16 h1 = __float2bfloat16(v.y);
            __nv_bfloat16 h2 = __float2bfloat16(v.z);
            __nv_bfloat16 h3 = __float2bfloat16(v.w);
            u32 hp0 = ((u32)__bfloat16_as_ushort(h1) << 16) | __bfloat16_as_ushort(h0);
            u32 hp1 = ((u32)__bfloat16_as_ushort(h3) << 16) | __bfloat16_as_ushort(h2);
            u32 lp0 = cvt2bf(v.x - __bfloat162float(h0), v.y - __bfloat162float(h1));
            u32 lp1 = cvt2bf(v.z - __bfloat162float(h2), v.w - __bfloat162float(h3));
            u32 off = (u32)(k * B_PITCH + nq * 8);
            *(u64*)(smem + S_BHI + off) = ((u64)hp1 << 32) | hp0;
            *(u64*)(smem + S_BLO + off) = ((u64)lp1 << 32) | lp0;
        }
        __syncthreads();

#pragma unroll
        for (int ks = 0; ks < 4; ks++) {
            u32 ahi[4][4], alo[4][4];
#pragma unroll
            for (int mt = 0; mt < 4; mt++) {
                u32 ao = aoff + (u32)(mt * 16 * A_PITCH + ks * 32);
                ldsm4(ahi[mt], sb + S_AHI + ao);
                ldsm4(alo[mt], sb + S_ALO + ao);
            }
#pragma unroll
            for (int ntp = 0; ntp < 4; ntp++) {
                u32 bo = boff + (u32)(ks * 16 * B_PITCH + ntp * 32);
                u32 bhi[4], blo[4];
                ldsm4t(bhi, sb + S_BHI + bo);
                ldsm4t(blo, sb + S_BLO + bo);
#pragma unroll
                for (int mt = 0; mt < 4; mt++) {
#pragma unroll
                    for (int h = 0; h < 2; h++) {
                        int nt = ntp * 2 + h;
                        float* d = &acc[(mt * 8 + nt) * 4];
                        mma16816(d, ahi[mt], &bhi[h * 2]);
                        mma16816(d, alo[mt], &bhi[h * 2]);
                        mma16816(d, ahi[mt], &blo[h * 2]);
                    }
                }
            }
        }
        __syncthreads();
    }

#pragma unroll
    for (int mt = 0; mt < 4; mt++) {
        int r0 = m0 + wm + mt * 16 + (l >> 2);
#pragma unroll
        for (int nt = 0; nt < 8; nt++) {
            int col = wn + nt * 8 + 2 * (l & 3);
            float2 bv = *(const float2*)(bias + col);
            const float* d = &acc[(mt * 8 + nt) * 4];
            float2 o0 = make_float2(d[0] + bv.x, d[1] + bv.y);
            float2 o1 = make_float2(d[2] + bv.x, d[3] + bv.y);
            *(float2*)(C + (size_t)r0 * NG + col)       = o0;
            *(float2*)(C + (size_t)(r0 + 8) * NG + col) = o1;
        }
    }
}

// ---------------------------------------------------------------------------
// Tensor-core recurrent kernel v2: 8 warps.
// 128 blocks x TB=16 batch rows, 256 threads.
// Warp w owns n-columns {8w..8w+7} + 64g (all 4 gates) — each thread holds
// zi/zf/zg/zo for its (row, unit) in registers. 48 MMAs/warp/step.
// U B-fragments preloaded via ldmatrix.x2.trans (64 regs), h hi/lo bf16
// double-buffered in smem, xz prefetched, 1 barrier/step.
// ---------------------------------------------------------------------------
#define RS_UHI 0
#define RS_ULO 33792                 // 64*528
#define RS_H   67584                 // 2 bufs x (hi 2304 + lo 2304)
#define REC_SMEM (67584 + 9216)      // 76800

template <int ACT>
__global__ __launch_bounds__(256, 1) void lstm_rec_mma(
    const float* __restrict__ xz, const float* __restrict__ U,
    float* __restrict__ hout)
{
    extern __shared__ char smem[];
    const u32 sb = smem_u32(smem);

    const int tid = threadIdx.x;
    const int w   = tid >> 5;          // 0..7
    const int l   = tid & 31;
    const int b0  = blockIdx.x * 16;

    // ---- stage U (64x256 fp32) -> hi/lo bf16, pitch 528 ----
#pragma unroll
    for (int i = 0; i < 16; i++) {
        int idx = tid + i * 256;          // 0..4095
        int k = idx >> 6, nq = idx & 63;
        float4 v = *(const float4*)(U + (size_t)k * NG + nq * 4);
        __nv_bfloat16 h0 = __float2bfloat16(v.x);
        __nv_bfloat16 h1 = __float2bfloat16(v.y);
        __nv_bfloat16 h2 = __float2bfloat16(v.z);
        __nv_bfloat16 h3 = __float2bfloat16(v.w);
        u32 hp0 = ((u32)__bfloat16_as_ushort(h1) << 16) | __bfloat16_as_ushort(h0);
        u32 hp1 = ((u32)__bfloat16_as_ushort(h3) << 16) | __bfloat16_as_ushort(h2);
        u32 lp0 = cvt2bf(v.x - __bfloat162float(h0), v.y - __bfloat162float(h1));
        u32 lp1 = cvt2bf(v.z - __bfloat162float(h2), v.w - __bfloat162float(h3));
        u32 off = (u32)(k * B_PITCH + nq * 8);
        *(u64*)(smem + RS_UHI + off) = ((u64)hp1 << 32) | hp0;
        *(u64*)(smem + RS_ULO + off) = ((u64)lp1 << 32) | lp0;
    }
    // zero both h buffers (2304 u32 words total)
#pragma unroll
    for (int i = 0; i < 9; i++)
        ((u32*)(smem + RS_H))[tid + i * 256] = 0;
    __syncthreads();

    // ---- preload B-fragments (U cols {8w..8w+7} + 64g) via ldmatrix.x2.trans
    u32 bh[4][4][2], bl[4][4][2];    // [gate][kstep][2 regs = 1 n8-tile]
    {
        const u32 brow = (u32)((l & 7) + ((l >> 3) & 1) * 8);
#pragma unroll
        for (int g = 0; g < 4; g++)
#pragma unroll
            for (int ks = 0; ks < 4; ks++) {
                u32 off = (ks * 16 + brow) * B_PITCH + (u32)(64 * g + 8 * w) * 2;
                ldsm2t(bh[g][ks], sb + RS_UHI + off);
                ldsm2t(bl[g][ks], sb + RS_ULO + off);
            }
    }

    // per-thread output ownership
    const int r   = l >> 2;               // rows r and r+8 (within 16)
    const int cq  = 2 * (l & 3);          // col pair within the n8 tile
    const int u0  = 8 * w + cq;           // owned h units u0, u0+1
    float c[4];
#pragma unroll
    for (int i = 0; i < 4; i++) c[i] = 0.f;

    // xz row base pointers
    const float* pA = xz + (size_t)(b0 + r)     * TSEQ * NG;
    const float* pB = xz + (size_t)(b0 + r + 8) * TSEQ * NG;

    // prefetch xz for t=0
    float xn[16];
#pragma unroll
    for (int g = 0; g < 4; g++) {
        int col = 64 * g + u0;
        float2 vA = *(const float2*)(pA + col);
        float2 vB = *(const float2*)(pB + col);
        xn[g * 4 + 0] = vA.x; xn[g * 4 + 1] = vA.y;
        xn[g * 4 + 2] = vB.x; xn[g * 4 + 3] = vB.y;
    }

    const u32 aoffb = (u32)(((l & 7) + ((l >> 3) & 1) * 8) * A_PITCH + (l >> 4) * 16);
    int buf = 0;
    __syncthreads();

    for (int t = 0; t < TSEQ; t++) {
        // acc := xz fragments
        float acc[16];
#pragma unroll
        for (int i = 0; i < 16; i++) acc[i] = xn[i];
        // prefetch next step
        if (t + 1 < TSEQ) {
#pragma unroll
            for (int g = 0; g < 4; g++) {
                int col = 64 * g + u0;
                float2 vA = *(const float2*)(pA + (size_t)(t + 1) * NG + col);
                float2 vB = *(const float2*)(pB + (size_t)(t + 1) * NG + col);
                xn[g * 4 + 0] = vA.x; xn[g * 4 + 1] = vA.y;
                xn[g * 4 + 2] = vB.x; xn[g * 4 + 3] = vB.y;
            }
        }

        // ---- MMAs: z += h_prev @ U (48 per warp) ----
        const u32 hbase = sb + RS_H + (u32)(buf * 4608);
#pragma unroll
        for (int ks = 0; ks < 4; ks++) {
            u32 ah[4], al[4];
            ldsm4(ah, hbase + aoffb + ks * 32);
            ldsm4(al, hbase + 2304 + aoffb + ks * 32);
#pragma unroll
            for (int g = 0; g < 4; g++) {
                float* d = &acc[g * 4];
                mma16816(d, ah, bh[g][ks]);
                mma16816(d, al, bh[g][ks]);
                mma16816(d, ah, bl[g][ks]);
            }
        }

        // ---- gates (in registers) + h writeback ----
        const u32 noff = RS_H + (u32)((buf ^ 1) * 4608);
#pragma unroll
        for (int r01 = 0; r01 < 2; r01++) {
            float hv[2];
#pragma unroll
            for (int e = 0; e < 2; e++) {
                int fi = r01 * 2 + e;
                float zi = acc[0 * 4 + fi];
                float zf = acc[1 * 4 + fi];
                float zg = acc[2 * 4 + fi];
                float zo = acc[3 * 4 + fi];
                float ig = sig_ap(zi);
                float fg = sig_ap(zf);
                float gg = (ACT == 0) ? tanh_ap(zg) : sig_ap(zg);
                float og = sig_ap(zo);
                int ci = r01 * 2 + e;
                c[ci] = fmaf(fg, c[ci], ig * gg);
                float ca = (ACT == 0) ? tanh_ap(c[ci]) : sig_ap(c[ci]);
                hv[e] = og * ca;
            }
            __nv_bfloat16 q0 = __float2bfloat16(hv[0]);
            __nv_bfloat16 q1 = __float2bfloat16(hv[1]);
            u32 hip = ((u32)__bfloat16_as_ushort(q1) << 16) | __bfloat16_as_ushort(q0);
            u32 lop = cvt2bf(hv[0] - __bfloat162float(q0),
                             hv[1] - __bfloat162float(q1));
            int row_s = r + 8 * r01;
            u32 hoff = (u32)(row_s * A_PITCH + u0 * 2);
            *(u32*)(smem + noff + hoff)        = hip;
            *(u32*)(smem + noff + 2304 + hoff) = lop;
            *(float2*)(hout + ((size_t)(b0 + row_s) * TSEQ + t) * HU + u0) =
                make_float2(hv[0], hv[1]);
        }
        __syncthreads();
        buf ^= 1;
    }
}

// ---------------------------------------------------------------------------
// Launch
// ---------------------------------------------------------------------------
extern "C" void kernel_launch(void* const* d_in, const int* in_sizes, int n_in,
                              void* d_out, int out_size)
{
    const float* x  = (const float*)d_in[0];
    const float* W1 = (const float*)d_in[1];
    const float* U1 = (const float*)d_in[2];
    const float* b1 = (const float*)d_in[3];
    const float* W2 = (const float*)d_in[4];
    const float* U2 = (const float*)d_in[5];
    const float* b2 = (const float*)d_in[6];
    float* out = (float*)d_out;

    void *xz_p = nullptr, *h1_p = nullptr;
    cudaGetSymbolAddress(&xz_p, g_xz);
    cudaGetSymbolAddress(&h1_p, g_h1);
    float* xz = (float*)xz_p;
    float* h1 = (float*)h1_p;

    cudaFuncSetAttribute(gemm_tc_kernel<128>,
                         cudaFuncAttributeMaxDynamicSharedMemorySize, GEMM_SMEM);
    cudaFuncSetAttribute(gemm_tc_kernel<64>,
                         cudaFuncAttributeMaxDynamicSharedMemorySize, GEMM_SMEM);
    cudaFuncSetAttribute(lstm_rec_mma<0>,
                         cudaFuncAttributeMaxDynamicSharedMemorySize, REC_SMEM);
    cudaFuncSetAttribute(lstm_rec_mma<1>,
                         cudaFuncAttributeMaxDynamicSharedMemorySize, REC_SMEM);

    // Layer 1
    gemm_tc_kernel<128><<<MTOT / 128, 256, GEMM_SMEM>>>(x, W1, b1, xz);
    lstm_rec_mma<0><<<BATCH / 16, 256, REC_SMEM>>>(xz, U1, h1);

    // Layer 2 (input = h1, K=64)
    gemm_tc_kernel<64><<<MTOT / 128, 256, GEMM_SMEM>>>(h1, W2, b2, xz);
    lstm_rec_mma<1><<<BATCH / 16, 256, REC_SMEM>>>(xz, U2, out);
}

// round 11
// speedup vs baseline: 3.3205x; 1.1292x over previous
#include <cuda_runtime.h>
#include <cuda_bf16.h>
#include <math.h>

// Problem constants
#define TSEQ 128
#define HU   64
#define NG   256
#define BATCH 2048
#define MTOT (BATCH*TSEQ)

typedef unsigned long long u64;
typedef unsigned int u32;

// Scratch (__device__ globals)
__device__ float g_xz[(size_t)MTOT * NG];   // xz buffer (reused by both layers)
__device__ float g_h1[(size_t)MTOT * HU];   // layer-1 hidden sequence

// ---------------------------------------------------------------------------
// Activation helpers
// ---------------------------------------------------------------------------
__device__ __forceinline__ float tanh_ap(float x) {
    float y; asm("tanh.approx.f32 %0, %1;" : "=f"(y) : "f"(x)); return y;
}
__device__ __forceinline__ float sig_ap(float x) {
    return fmaf(0.5f, tanh_ap(0.5f * x), 0.5f);
}

// ---------------------------------------------------------------------------
// mma.sync / ldmatrix helpers (baseline PTX ISA — valid on plain sm_103)
// ---------------------------------------------------------------------------
__device__ __forceinline__ u32 smem_u32(const void* p) {
    u32 a;
    asm("{ .reg .u64 t; cvta.to.shared.u64 t, %1; cvt.u32.u64 %0, t; }"
        : "=r"(a) : "l"(p));
    return a;
}
__device__ __forceinline__ void ldsm4(u32 r[4], u32 addr) {
    asm volatile("ldmatrix.sync.aligned.m8n8.x4.shared.b16 {%0,%1,%2,%3}, [%4];"
                 : "=r"(r[0]), "=r"(r[1]), "=r"(r[2]), "=r"(r[3]) : "r"(addr));
}
__device__ __forceinline__ void ldsm4t(u32 r[4], u32 addr) {
    asm volatile("ldmatrix.sync.aligned.m8n8.x4.trans.shared.b16 {%0,%1,%2,%3}, [%4];"
                 : "=r"(r[0]), "=r"(r[1]), "=r"(r[2]), "=r"(r[3]) : "r"(addr));
}
__device__ __forceinline__ void ldsm2t(u32 r[2], u32 addr) {
    asm volatile("ldmatrix.sync.aligned.m8n8.x2.trans.shared.b16 {%0,%1}, [%2];"
                 : "=r"(r[0]), "=r"(r[1]) : "r"(addr));
}
__device__ __forceinline__ void mma16816(float d[4], const u32 a[4], const u32 b[2]) {
    asm volatile(
        "mma.sync.aligned.m16n8k16.row.col.f32.bf16.bf16.f32 "
        "{%0,%1,%2,%3}, {%4,%5,%6,%7}, {%8,%9}, {%0,%1,%2,%3};"
        : "+f"(d[0]), "+f"(d[1]), "+f"(d[2]), "+f"(d[3])
        : "r"(a[0]), "r"(a[1]), "r"(a[2]), "r"(a[3]), "r"(b[0]), "r"(b[1]));
}
// pack two fp32 -> bf16x2 (first arg in lower half)
__device__ __forceinline__ u32 cvt2bf(float lo, float hi) {
    u32 r; asm("cvt.rn.bf16x2.f32 %0, %1, %2;" : "=r"(r) : "f"(hi), "f"(lo));
    return r;
}

// ---------------------------------------------------------------------------
// Tensor-core GEMM (HMMA): C[M,256] = A[M,KF32] @ W[KF32,256] + bias
// (unchanged from R8: passing at rel_err 1.3e-6)
// ---------------------------------------------------------------------------
#define A_PITCH 144
#define B_PITCH 528
#define S_AHI 0
#define S_ALO (128 * A_PITCH)
#define S_BHI (2 * 128 * A_PITCH)
#define S_BLO (2 * 128 * A_PITCH + 64 * B_PITCH)
#define GEMM_SMEM (2 * 128 * A_PITCH + 2 * 64 * B_PITCH)  // 104448

template <int KF32>
__global__ __launch_bounds__(256, 1) void gemm_tc_kernel(
    const float* __restrict__ A, const float* __restrict__ W,
    const float* __restrict__ bias, float* __restrict__ C)
{
    extern __shared__ char smem[];
    const u32 sb = smem_u32(smem);

    const int tid = threadIdx.x;
    const int wid = tid >> 5;
    const int l   = tid & 31;
    const int m0  = blockIdx.x * 128;
    const int wm  = (wid >> 2) * 64;
    const int wn  = (wid & 3) * 64;

    float acc[128];
#pragma unroll
    for (int i = 0; i < 128; i++) acc[i] = 0.f;

    const u32 aoff = (u32)((wm + (l & 7) + ((l >> 3) & 1) * 8) * A_PITCH + (l >> 4) * 16);
    const u32 boff = (u32)(((l & 7) + ((l >> 3) & 1) * 8) * B_PITCH + (wn + (l >> 4) * 8) * 2);

    const int NCHUNK = KF32 / 64;
    for (int kc = 0; kc < NCHUNK; kc++) {
        const int k0 = kc * 64;

        const float* Ab = A + (size_t)m0 * KF32 + k0;
#pragma unroll
        for (int i = 0; i < 8; i++) {
            int idx = tid + i * 256;
            int m = idx >> 4, kq = idx & 15;
            float4 v = *(const float4*)(Ab + (size_t)m * KF32 + kq * 4);
            __nv_bfloat16 h0 = __float2bfloat16(v.x);
            __nv_bfloat16 h1 = __float2bfloat16(v.y);
            __nv_bfloat16 h2 = __float2bfloat16(v.z);
            __nv_bfloat16 h3 = __float2bfloat16(v.w);
            u32 hp0 = ((u32)__bfloat16_as_ushort(h1) << 16) | __bfloat16_as_ushort(h0);
            u32 hp1 = ((u32)__bfloat16_as_ushort(h3) << 16) | __bfloat16_as_ushort(h2);
            u32 lp0 = cvt2bf(v.x - __bfloat162float(h0), v.y - __bfloat162float(h1));
            u32 lp1 = cvt2bf(v.z - __bfloat162float(h2), v.w - __bfloat162float(h3));
            u32 off = (u32)(m * A_PITCH + kq * 8);
            *(u64*)(smem + S_AHI + off) = ((u64)hp1 << 32) | hp0;
            *(u64*)(smem + S_ALO + off) = ((u64)lp1 << 32) | lp0;
        }
        const float* Wb = W + (size_t)k0 * NG;
#pragma unroll
        for (int i = 0; i < 16; i++) {
            int idx = tid + i * 256;
            int k = idx >> 6, nq = idx & 63;
            float4 v = *(const float4*)(Wb + (size_t)k * NG + nq * 4);
            __nv_bfloat16 h0 = __float2bfloat16(v.x);
            __nv_bfloat16 h1 = __float2bfloat16(v.y);
            __nv_bfloat16 h2 = __float2bfloat16(v.z);
            __nv_bfloat16 h3 = __float2bfloat16(v.w);
            u32 hp0 = ((u32)__bfloat16_as_ushort(h1) << 16) | __bfloat16_as_ushort(h0);
            u32 hp1 = ((u32)__bfloat16_as_ushort(h3) << 16) | __bfloat16_as_ushort(h2);
            u32 lp0 = cvt2bf(v.x - __bfloat162float(h0), v.y - __bfloat162float(h1));
            u32 lp1 = cvt2bf(v.z - __bfloat162float(h2), v.w - __bfloat162float(h3));
            u32 off = (u32)(k * B_PITCH + nq * 8);
            *(u64*)(smem + S_BHI + off) = ((u64)hp1 << 32) | hp0;
            *(u64*)(smem + S_BLO + off) = ((u64)lp1 << 32) | lp0;
        }
        __syncthreads();

#pragma unroll
        for (int ks = 0; ks < 4; ks++) {
            u32 ahi[4][4], alo[4][4];
#pragma unroll
            for (int mt = 0; mt < 4; mt++) {
                u32 ao = aoff + (u32)(mt * 16 * A_PITCH + ks * 32);
                ldsm4(ahi[mt], sb + S_AHI + ao);
                ldsm4(alo[mt], sb + S_ALO + ao);
            }
#pragma unroll
            for (int ntp = 0; ntp < 4; ntp++) {
                u32 bo = boff + (u32)(ks * 16 * B_PITCH + ntp * 32);
                u32 bhi[4], blo[4];
                ldsm4t(bhi, sb + S_BHI + bo);
                ldsm4t(blo, sb + S_BLO + bo);
#pragma unroll
                for (int mt = 0; mt < 4; mt++) {
#pragma unroll
                    for (int h = 0; h < 2; h++) {
                        int nt = ntp * 2 + h;
                        float* d = &acc[(mt * 8 + nt) * 4];
                        mma16816(d, ahi[mt], &bhi[h * 2]);
                        mma16816(d, alo[mt], &bhi[h * 2]);
                        mma16816(d, ahi[mt], &blo[h * 2]);
                    }
                }
            }
        }
        __syncthreads();
    }

#pragma unroll
    for (int mt = 0; mt < 4; mt++) {
        int r0 = m0 + wm + mt * 16 + (l >> 2);
#pragma unroll
        for (int nt = 0; nt < 8; nt++) {
            int col = wn + nt * 8 + 2 * (l & 3);
            float2 bv = *(const float2*)(bias + col);
            const float* d = &acc[(mt * 8 + nt) * 4];
            float2 o0 = make_float2(d[0] + bv.x, d[1] + bv.y);
            float2 o1 = make_float2(d[2] + bv.x, d[3] + bv.y);
            *(float2*)(C + (size_t)r0 * NG + col)       = o0;
            *(float2*)(C + (size_t)(r0 + 8) * NG + col) = o1;
        }
    }
}

// ---------------------------------------------------------------------------
// Tensor-core recurrent kernel v3: 8 warps, split accumulator chains.
// 128 blocks x TB=16 batch rows, 256 threads.
// Warp w owns n-columns {8w..8w+7} + 64g (all 4 gates).
// Per step: hoist all 8 h-ldmatrix, then 48 MMAs into THREE independent
// accumulator sets (hh seeded with xz, lh, hl) -> dep chains of 4, not 12.
// ---------------------------------------------------------------------------
#define RS_UHI 0
#define RS_ULO 33792                 // 64*528
#define RS_H   67584                 // 2 bufs x (hi 2304 + lo 2304)
#define REC_SMEM (67584 + 9216)      // 76800

template <int ACT>
__global__ __launch_bounds__(256, 1) void lstm_rec_mma(
    const float* __restrict__ xz, const float* __restrict__ U,
    float* __restrict__ hout)
{
    extern __shared__ char smem[];
    const u32 sb = smem_u32(smem);

    const int tid = threadIdx.x;
    const int w   = tid >> 5;          // 0..7
    const int l   = tid & 31;
    const int b0  = blockIdx.x * 16;

    // ---- stage U (64x256 fp32) -> hi/lo bf16, pitch 528 ----
#pragma unroll
    for (int i = 0; i < 16; i++) {
        int idx = tid + i * 256;          // 0..4095
        int k = idx >> 6, nq = idx & 63;
        float4 v = *(const float4*)(U + (size_t)k * NG + nq * 4);
        __nv_bfloat16 h0 = __float2bfloat16(v.x);
        __nv_bfloat16 h1 = __float2bfloat16(v.y);
        __nv_bfloat16 h2 = __float2bfloat16(v.z);
        __nv_bfloat16 h3 = __float2bfloat16(v.w);
        u32 hp0 = ((u32)__bfloat16_as_ushort(h1) << 16) | __bfloat16_as_ushort(h0);
        u32 hp1 = ((u32)__bfloat16_as_ushort(h3) << 16) | __bfloat16_as_ushort(h2);
        u32 lp0 = cvt2bf(v.x - __bfloat162float(h0), v.y - __bfloat162float(h1));
        u32 lp1 = cvt2bf(v.z - __bfloat162float(h2), v.w - __bfloat162float(h3));
        u32 off = (u32)(k * B_PITCH + nq * 8);
        *(u64*)(smem + RS_UHI + off) = ((u64)hp1 << 32) | hp0;
        *(u64*)(smem + RS_ULO + off) = ((u64)lp1 << 32) | lp0;
    }
    // zero both h buffers
#pragma unroll
    for (int i = 0; i < 9; i++)
        ((u32*)(smem + RS_H))[tid + i * 256] = 0;
    __syncthreads();

    // ---- preload B-fragments (U cols {8w..8w+7} + 64g) via ldmatrix.x2.trans
    u32 bh[4][4][2], bl[4][4][2];    // [gate][kstep][2 regs]
    {
        const u32 brow = (u32)((l & 7) + ((l >> 3) & 1) * 8);
#pragma unroll
        for (int g = 0; g < 4; g++)
#pragma unroll
            for (int ks = 0; ks < 4; ks++) {
                u32 off = (ks * 16 + brow) * B_PITCH + (u32)(64 * g + 8 * w) * 2;
                ldsm2t(bh[g][ks], sb + RS_UHI + off);
                ldsm2t(bl[g][ks], sb + RS_ULO + off);
            }
    }

    // per-thread output ownership
    const int r   = l >> 2;               // rows r and r+8 (within 16)
    const int cq  = 2 * (l & 3);
    const int u0  = 8 * w + cq;           // owned h units u0, u0+1
    float c[4];
#pragma unroll
    for (int i = 0; i < 4; i++) c[i] = 0.f;

    const float* pA = xz + (size_t)(b0 + r)     * TSEQ * NG;
    const float* pB = xz + (size_t)(b0 + r + 8) * TSEQ * NG;

    // prefetch xz for t=0
    float xn[16];
#pragma unroll
    for (int g = 0; g < 4; g++) {
        int col = 64 * g + u0;
        float2 vA = *(const float2*)(pA + col);
        float2 vB = *(const float2*)(pB + col);
        xn[g * 4 + 0] = vA.x; xn[g * 4 + 1] = vA.y;
        xn[g * 4 + 2] = vB.x; xn[g * 4 + 3] = vB.y;
    }

    const u32 aoffb = (u32)(((l & 7) + ((l >> 3) & 1) * 8) * A_PITCH + (l >> 4) * 16);
    int buf = 0;
    __syncthreads();

    for (int t = 0; t < TSEQ; t++) {
        // ---- hoist ALL h fragment loads (independent latencies overlap) ----
        const u32 hbase = sb + RS_H + (u32)(buf * 4608);
        u32 ah[4][4], al[4][4];
#pragma unroll
        for (int ks = 0; ks < 4; ks++) {
            ldsm4(ah[ks], hbase + aoffb + ks * 32);
            ldsm4(al[ks], hbase + 2304 + aoffb + ks * 32);
        }

        // ---- three independent accumulator chains (len 4 each) ----
        float hh[16], lh[16], hl[16];
#pragma unroll
        for (int i = 0; i < 16; i++) { hh[i] = xn[i]; lh[i] = 0.f; hl[i] = 0.f; }

#pragma unroll
        for (int ks = 0; ks < 4; ks++) {
#pragma unroll
            for (int g = 0; g < 4; g++) {
                mma16816(&hh[g * 4], ah[ks], bh[g][ks]);
                mma16816(&lh[g * 4], al[ks], bh[g][ks]);
                mma16816(&hl[g * 4], ah[ks], bl[g][ks]);
            }
        }

        // prefetch next xz during MMA drain
        if (t + 1 < TSEQ) {
#pragma unroll
            for (int g = 0; g < 4; g++) {
                int col = 64 * g + u0;
                float2 vA = *(const float2*)(pA + (size_t)(t + 1) * NG + col);
                float2 vB = *(const float2*)(pB + (size_t)(t + 1) * NG + col);
                xn[g * 4 + 0] = vA.x; xn[g * 4 + 1] = vA.y;
                xn[g * 4 + 2] = vB.x; xn[g * 4 + 3] = vB.y;
            }
        }

        // ---- combine + gates + h writeback ----
        const u32 noff = RS_H + (u32)((buf ^ 1) * 4608);
#pragma unroll
        for (int r01 = 0; r01 < 2; r01++) {
            float hv[2];
#pragma unroll
            for (int e = 0; e < 2; e++) {
                int fi = r01 * 2 + e;
                float zi = hh[0 * 4 + fi] + lh[0 * 4 + fi] + hl[0 * 4 + fi];
                float zf = hh[1 * 4 + fi] + lh[1 * 4 + fi] + hl[1 * 4 + fi];
                float zg = hh[2 * 4 + fi] + lh[2 * 4 + fi] + hl[2 * 4 + fi];
                float zo = hh[3 * 4 + fi] + lh[3 * 4 + fi] + hl[3 * 4 + fi];
                float ig = sig_ap(zi);
                float fg = sig_ap(zf);
                float gg = (ACT == 0) ? tanh_ap(zg) : sig_ap(zg);
                float og = sig_ap(zo);
                int ci = r01 * 2 + e;
                c[ci] = fmaf(fg, c[ci], ig * gg);
                float ca = (ACT == 0) ? tanh_ap(c[ci]) : sig_ap(c[ci]);
                hv[e] = og * ca;
            }
            __nv_bfloat16 q0 = __float2bfloat16(hv[0]);
            __nv_bfloat16 q1 = __float2bfloat16(hv[1]);
            u32 hip = ((u32)__bfloat16_as_ushort(q1) << 16) | __bfloat16_as_ushort(q0);
            u32 lop = cvt2bf(hv[0] - __bfloat162float(q0),
                             hv[1] - __bfloat162float(q1));
            int row_s = r + 8 * r01;
            u32 hoff = (u32)(row_s * A_PITCH + u0 * 2);
            *(u32*)(smem + noff + hoff)        = hip;
            *(u32*)(smem + noff + 2304 + hoff) = lop;
            *(float2*)(hout + ((size_t)(b0 + row_s) * TSEQ + t) * HU + u0) =
                make_float2(hv[0], hv[1]);
        }
        __syncthreads();
        buf ^= 1;
    }
}

// ---------------------------------------------------------------------------
// Launch
// ---------------------------------------------------------------------------
extern "C" void kernel_launch(void* const* d_in, const int* in_sizes, int n_in,
                              void* d_out, int out_size)
{
    const float* x  = (const float*)d_in[0];
    const float* W1 = (const float*)d_in[1];
    const float* U1 = (const float*)d_in[2];
    const float* b1 = (const float*)d_in[3];
    const float* W2 = (const float*)d_in[4];
    const float* U2 = (const float*)d_in[5];
    const float* b2 = (const float*)d_in[6];
    float* out = (float*)d_out;

    void *xz_p = nullptr, *h1_p = nullptr;
    cudaGetSymbolAddress(&xz_p, g_xz);
    cudaGetSymbolAddress(&h1_p, g_h1);
    float* xz = (float*)xz_p;
    float* h1 = (float*)h1_p;

    cudaFuncSetAttribute(gemm_tc_kernel<128>,
                         cudaFuncAttributeMaxDynamicSharedMemorySize, GEMM_SMEM);
    cudaFuncSetAttribute(gemm_tc_kernel<64>,
                         cudaFuncAttributeMaxDynamicSharedMemorySize, GEMM_SMEM);
    cudaFuncSetAttribute(lstm_rec_mma<0>,
                         cudaFuncAttributeMaxDynamicSharedMemorySize, REC_SMEM);
    cudaFuncSetAttribute(lstm_rec_mma<1>,
                         cudaFuncAttributeMaxDynamicSharedMemorySize, REC_SMEM);

    // Layer 1
    gemm_tc_kernel<128><<<MTOT / 128, 256, GEMM_SMEM>>>(x, W1, b1, xz);
    lstm_rec_mma<0><<<BATCH / 16, 256, REC_SMEM>>>(xz, U1, h1);

    // Layer 2 (input = h1, K=64)
    gemm_tc_kernel<64><<<MTOT / 128, 256, GEMM_SMEM>>>(h1, W2, b2, xz);
    lstm_rec_mma<1><<<BATCH / 16, 256, REC_SMEM>>>(xz, U2, out);
}

// round 12
// speedup vs baseline: 3.4124x; 1.0277x over previous
#include <cuda_runtime.h>
#include <cuda_bf16.h>
#include <math.h>

// Problem constants
#define TSEQ 128
#define HU   64
#define NG   256
#define BATCH 2048
#define MTOT (BATCH*TSEQ)

typedef unsigned long long u64;
typedef unsigned int u32;

// Scratch (__device__ globals)
__device__ float g_xz[(size_t)MTOT * NG];   // xz buffer (reused by both layers)
__device__ float g_h1[(size_t)MTOT * HU];   // layer-1 hidden sequence

// ---------------------------------------------------------------------------
// Activation helpers
// ---------------------------------------------------------------------------
__device__ __forceinline__ float tanh_ap(float x) {
    float y; asm("tanh.approx.f32 %0, %1;" : "=f"(y) : "f"(x)); return y;
}
__device__ __forceinline__ float sig_ap(float x) {
    return fmaf(0.5f, tanh_ap(0.5f * x), 0.5f);
}

// ---------------------------------------------------------------------------
// mma.sync / ldmatrix helpers (baseline PTX ISA — valid on plain sm_103)
// ---------------------------------------------------------------------------
__device__ __forceinline__ u32 smem_u32(const void* p) {
    u32 a;
    asm("{ .reg .u64 t; cvta.to.shared.u64 t, %1; cvt.u32.u64 %0, t; }"
        : "=r"(a) : "l"(p));
    return a;
}
__device__ __forceinline__ void ldsm4(u32 r[4], u32 addr) {
    asm volatile("ldmatrix.sync.aligned.m8n8.x4.shared.b16 {%0,%1,%2,%3}, [%4];"
                 : "=r"(r[0]), "=r"(r[1]), "=r"(r[2]), "=r"(r[3]) : "r"(addr));
}
__device__ __forceinline__ void ldsm4t(u32 r[4], u32 addr) {
    asm volatile("ldmatrix.sync.aligned.m8n8.x4.trans.shared.b16 {%0,%1,%2,%3}, [%4];"
                 : "=r"(r[0]), "=r"(r[1]), "=r"(r[2]), "=r"(r[3]) : "r"(addr));
}
__device__ __forceinline__ void ldsm2t(u32 r[2], u32 addr) {
    asm volatile("ldmatrix.sync.aligned.m8n8.x2.trans.shared.b16 {%0,%1}, [%2];"
                 : "=r"(r[0]), "=r"(r[1]) : "r"(addr));
}
__device__ __forceinline__ void mma16816(float d[4], const u32 a[4], const u32 b[2]) {
    asm volatile(
        "mma.sync.aligned.m16n8k16.row.col.f32.bf16.bf16.f32 "
        "{%0,%1,%2,%3}, {%4,%5,%6,%7}, {%8,%9}, {%0,%1,%2,%3};"
        : "+f"(d[0]), "+f"(d[1]), "+f"(d[2]), "+f"(d[3])
        : "r"(a[0]), "r"(a[1]), "r"(a[2]), "r"(a[3]), "r"(b[0]), "r"(b[1]));
}
// pack two fp32 -> bf16x2 (first arg in lower half)
__device__ __forceinline__ u32 cvt2bf(float lo, float hi) {
    u32 r; asm("cvt.rn.bf16x2.f32 %0, %1, %2;" : "=r"(r) : "f"(hi), "f"(lo));
    return r;
}

// ---------------------------------------------------------------------------
// Tensor-core GEMM (HMMA) v2: C[M,256] = A[M,KF32] @ W[KF32,256] + bias
// N split across CTAs: tile 128M x 128N, grid (M/128, 2) -> 70 KB smem
// -> 2 CTAs/SM: staging of one CTA overlaps MMAs of the other.
// Split-fp32: D = a_hi*b_hi + a_lo*b_hi + a_hi*b_lo (bf16, fp32 acc).
// ---------------------------------------------------------------------------
#define A_PITCH 144          // 36 words, 4-bank/row shift: conflict-free
#define B_PITCH 272          // 68 words, 4-bank/row shift: conflict-free
#define S_AHI 0
#define S_ALO (128 * A_PITCH)                     // 18432
#define S_BHI (2 * 128 * A_PITCH)                 // 36864
#define S_BLO (2 * 128 * A_PITCH + 64 * B_PITCH)  // 54272
#define GEMM_SMEM (2 * 128 * A_PITCH + 2 * 64 * B_PITCH)  // 71680

template <int KF32>
__global__ __launch_bounds__(256, 2) void gemm_tc_kernel(
    const float* __restrict__ A, const float* __restrict__ W,
    const float* __restrict__ bias, float* __restrict__ C)
{
    extern __shared__ char smem[];
    const u32 sb = smem_u32(smem);

    const int tid = threadIdx.x;
    const int wid = tid >> 5;
    const int l   = tid & 31;
    const int m0  = blockIdx.x * 128;
    const int n0  = blockIdx.y * 128;
    const int wm  = (wid >> 2) * 64;     // warp M offset (0/64)
    const int wn  = (wid & 3) * 32;      // warp N offset within 128

    float acc[64];
#pragma unroll
    for (int i = 0; i < 64; i++) acc[i] = 0.f;

    const u32 aoff = (u32)((wm + (l & 7) + ((l >> 3) & 1) * 8) * A_PITCH + (l >> 4) * 16);
    const u32 boff = (u32)(((l & 7) + ((l >> 3) & 1) * 8) * B_PITCH + (wn + (l >> 4) * 8) * 2);

    const int NCHUNK = KF32 / 64;
    for (int kc = 0; kc < NCHUNK; kc++) {
        const int k0 = kc * 64;

        // ---- stage A chunk: [128][64] fp32 -> hi/lo bf16 ----
        const float* Ab = A + (size_t)m0 * KF32 + k0;
#pragma unroll
        for (int i = 0; i < 8; i++) {
            int idx = tid + i * 256;          // 0..2047
            int m = idx >> 4, kq = idx & 15;  // k = kq*4
            float4 v = *(const float4*)(Ab + (size_t)m * KF32 + kq * 4);
            __nv_bfloat16 h0 = __float2bfloat16(v.x);
            __nv_bfloat16 h1 = __float2bfloat16(v.y);
            __nv_bfloat16 h2 = __float2bfloat16(v.z);
            __nv_bfloat16 h3 = __float2bfloat16(v.w);
            u32 hp0 = ((u32)__bfloat16_as_ushort(h1) << 16) | __bfloat16_as_ushort(h0);
            u32 hp1 = ((u32)__bfloat16_as_ushort(h3) << 16) | __bfloat16_as_ushort(h2);
            u32 lp0 = cvt2bf(v.x - __bfloat162float(h0), v.y - __bfloat162float(h1));
            u32 lp1 = cvt2bf(v.z - __bfloat162float(h2), v.w - __bfloat162float(h3));
            u32 off = (u32)(m * A_PITCH + kq * 8);
            *(u64*)(smem + S_AHI + off) = ((u64)hp1 << 32) | hp0;
            *(u64*)(smem + S_ALO + off) = ((u64)lp1 << 32) | lp0;
        }
        // ---- stage B chunk: W[k0+k][n0+n], [64][128] fp32 -> hi/lo bf16 ----
        const float* Wb = W + (size_t)k0 * NG + n0;
#pragma unroll
        for (int i = 0; i < 8; i++) {
            int idx = tid + i * 256;          // 0..2047
            int k = idx >> 5, nq = idx & 31;  // n = nq*4
            float4 v = *(const float4*)(Wb + (size_t)k * NG + nq * 4);
            __nv_bfloat16 h0 = __float2bfloat16(v.x);
            __nv_bfloat16 h1 = __float2bfloat16(v.y);
            __nv_bfloat16 h2 = __float2bfloat16(v.z);
            __nv_bfloat16 h3 = __float2bfloat16(v.w);
            u32 hp0 = ((u32)__bfloat16_as_ushort(h1) << 16) | __bfloat16_as_ushort(h0);
            u32 hp1 = ((u32)__bfloat16_as_ushort(h3) << 16) | __bfloat16_as_ushort(h2);
            u32 lp0 = cvt2bf(v.x - __bfloat162float(h0), v.y - __bfloat162float(h1));
            u32 lp1 = cvt2bf(v.z - __bfloat162float(h2), v.w - __bfloat162float(h3));
            u32 off = (u32)(k * B_PITCH + nq * 8);
            *(u64*)(smem + S_BHI + off) = ((u64)hp1 << 32) | hp0;
            *(u64*)(smem + S_BLO + off) = ((u64)lp1 << 32) | lp0;
        }
        __syncthreads();

        // ---- MMA over 4 k16 steps: warp tile 64x32 ----
#pragma unroll
        for (int ks = 0; ks < 4; ks++) {
            u32 ahi[4][4], alo[4][4];
#pragma unroll
            for (int mt = 0; mt < 4; mt++) {
                u32 ao = aoff + (u32)(mt * 16 * A_PITCH + ks * 32);
                ldsm4(ahi[mt], sb + S_AHI + ao);
                ldsm4(alo[mt], sb + S_ALO + ao);
            }
#pragma unroll
            for (int ntp = 0; ntp < 2; ntp++) {
                u32 bo = boff + (u32)(ks * 16 * B_PITCH + ntp * 32);
                u32 bhi[4], blo[4];
                ldsm4t(bhi, sb + S_BHI + bo);
                ldsm4t(blo, sb + S_BLO + bo);
#pragma unroll
                for (int mt = 0; mt < 4; mt++) {
#pragma unroll
                    for (int h = 0; h < 2; h++) {
                        int nt = ntp * 2 + h;
                        float* d = &acc[(mt * 4 + nt) * 4];
                        mma16816(d, ahi[mt], &bhi[h * 2]);
                        mma16816(d, alo[mt], &bhi[h * 2]);
                        mma16816(d, ahi[mt], &blo[h * 2]);
                    }
                }
            }
        }
        __syncthreads();
    }

    // ---- epilogue: bias + store ----
#pragma unroll
    for (int mt = 0; mt < 4; mt++) {
        int r0 = m0 + wm + mt * 16 + (l >> 2);
#pragma unroll
        for (int nt = 0; nt < 4; nt++) {
            int col = n0 + wn + nt * 8 + 2 * (l & 3);
            float2 bv = *(const float2*)(bias + col);
            const float* d = &acc[(mt * 4 + nt) * 4];
            float2 o0 = make_float2(d[0] + bv.x, d[1] + bv.y);
            float2 o1 = make_float2(d[2] + bv.x, d[3] + bv.y);
            *(float2*)(C + (size_t)r0 * NG + col)       = o0;
            *(float2*)(C + (size_t)(r0 + 8) * NG + col) = o1;
        }
    }
}

// ---------------------------------------------------------------------------
// Tensor-core recurrent kernel (unchanged from R11: 127 us/layer).
// ---------------------------------------------------------------------------
#define RB_PITCH 528
#define RS_UHI 0
#define RS_ULO 33792                 // 64*528
#define RS_H   67584                 // 2 bufs x (hi 2304 + lo 2304)
#define REC_SMEM (67584 + 9216)      // 76800

template <int ACT>
__global__ __launch_bounds__(256, 1) void lstm_rec_mma(
    const float* __restrict__ xz, const float* __restrict__ U,
    float* __restrict__ hout)
{
    extern __shared__ char smem[];
    const u32 sb = smem_u32(smem);

    const int tid = threadIdx.x;
    const int w   = tid >> 5;          // 0..7
    const int l   = tid & 31;
    const int b0  = blockIdx.x * 16;

    // ---- stage U (64x256 fp32) -> hi/lo bf16, pitch 528 ----
#pragma unroll
    for (int i = 0; i < 16; i++) {
        int idx = tid + i * 256;          // 0..4095
        int k = idx >> 6, nq = idx & 63;
        float4 v = *(const float4*)(U + (size_t)k * NG + nq * 4);
        __nv_bfloat16 h0 = __float2bfloat16(v.x);
        __nv_bfloat16 h1 = __float2bfloat16(v.y);
        __nv_bfloat16 h2 = __float2bfloat16(v.z);
        __nv_bfloat16 h3 = __float2bfloat16(v.w);
        u32 hp0 = ((u32)__bfloat16_as_ushort(h1) << 16) | __bfloat16_as_ushort(h0);
        u32 hp1 = ((u32)__bfloat16_as_ushort(h3) << 16) | __bfloat16_as_ushort(h2);
        u32 lp0 = cvt2bf(v.x - __bfloat162float(h0), v.y - __bfloat162float(h1));
        u32 lp1 = cvt2bf(v.z - __bfloat162float(h2), v.w - __bfloat162float(h3));
        u32 off = (u32)(k * RB_PITCH + nq * 8);
        *(u64*)(smem + RS_UHI + off) = ((u64)hp1 << 32) | hp0;
        *(u64*)(smem + RS_ULO + off) = ((u64)lp1 << 32) | lp0;
    }
    // zero both h buffers
#pragma unroll
    for (int i = 0; i < 9; i++)
        ((u32*)(smem + RS_H))[tid + i * 256] = 0;
    __syncthreads();

    // ---- preload B-fragments (U cols {8w..8w+7} + 64g) via ldmatrix.x2.trans
    u32 bh[4][4][2], bl[4][4][2];    // [gate][kstep][2 regs]
    {
        const u32 brow = (u32)((l & 7) + ((l >> 3) & 1) * 8);
#pragma unroll
        for (int g = 0; g < 4; g++)
#pragma unroll
            for (int ks = 0; ks < 4; ks++) {
                u32 off = (ks * 16 + brow) * RB_PITCH + (u32)(64 * g + 8 * w) * 2;
                ldsm2t(bh[g][ks], sb + RS_UHI + off);
                ldsm2t(bl[g][ks], sb + RS_ULO + off);
            }
    }

    // per-thread output ownership
    const int r   = l >> 2;               // rows r and r+8 (within 16)
    const int cq  = 2 * (l & 3);
    const int u0  = 8 * w + cq;           // owned h units u0, u0+1
    float c[4];
#pragma unroll
    for (int i = 0; i < 4; i++) c[i] = 0.f;

    const float* pA = xz + (size_t)(b0 + r)     * TSEQ * NG;
    const float* pB = xz + (size_t)(b0 + r + 8) * TSEQ * NG;

    // prefetch xz for t=0
    float xn[16];
#pragma unroll
    for (int g = 0; g < 4; g++) {
        int col = 64 * g + u0;
        float2 vA = *(const float2*)(pA + col);
        float2 vB = *(const float2*)(pB + col);
        xn[g * 4 + 0] = vA.x; xn[g * 4 + 1] = vA.y;
        xn[g * 4 + 2] = vB.x; xn[g * 4 + 3] = vB.y;
    }

    const u32 aoffb = (u32)(((l & 7) + ((l >> 3) & 1) * 8) * A_PITCH + (l >> 4) * 16);
    int buf = 0;
    __syncthreads();

    for (int t = 0; t < TSEQ; t++) {
        // ---- hoist ALL h fragment loads ----
        const u32 hbase = sb + RS_H + (u32)(buf * 4608);
        u32 ah[4][4], al[4][4];
#pragma unroll
        for (int ks = 0; ks < 4; ks++) {
            ldsm4(ah[ks], hbase + aoffb + ks * 32);
            ldsm4(al[ks], hbase + 2304 + aoffb + ks * 32);
        }

        // ---- three independent accumulator chains ----
        float hh[16], lh[16], hl[16];
#pragma unroll
        for (int i = 0; i < 16; i++) { hh[i] = xn[i]; lh[i] = 0.f; hl[i] = 0.f; }

#pragma unroll
        for (int ks = 0; ks < 4; ks++) {
#pragma unroll
            for (int g = 0; g < 4; g++) {
                mma16816(&hh[g * 4], ah[ks], bh[g][ks]);
                mma16816(&lh[g * 4], al[ks], bh[g][ks]);
                mma16816(&hl[g * 4], ah[ks], bl[g][ks]);
            }
        }

        // prefetch next xz during MMA drain
        if (t + 1 < TSEQ) {
#pragma unroll
            for (int g = 0; g < 4; g++) {
                int col = 64 * g + u0;
                float2 vA = *(const float2*)(pA + (size_t)(t + 1) * NG + col);
                float2 vB = *(const float2*)(pB + (size_t)(t + 1) * NG + col);
                xn[g * 4 + 0] = vA.x; xn[g * 4 + 1] = vA.y;
                xn[g * 4 + 2] = vB.x; xn[g * 4 + 3] = vB.y;
            }
        }

        // ---- combine + gates + h writeback ----
        const u32 noff = RS_H + (u32)((buf ^ 1) * 4608);
#pragma unroll
        for (int r01 = 0; r01 < 2; r01++) {
            float hv[2];
#pragma unroll
            for (int e = 0; e < 2; e++) {
                int fi = r01 * 2 + e;
                float zi = hh[0 * 4 + fi] + lh[0 * 4 + fi] + hl[0 * 4 + fi];
                float zf = hh[1 * 4 + fi] + lh[1 * 4 + fi] + hl[1 * 4 + fi];
                float zg = hh[2 * 4 + fi] + lh[2 * 4 + fi] + hl[2 * 4 + fi];
                float zo = hh[3 * 4 + fi] + lh[3 * 4 + fi] + hl[3 * 4 + fi];
                float ig = sig_ap(zi);
                float fg = sig_ap(zf);
                float gg = (ACT == 0) ? tanh_ap(zg) : sig_ap(zg);
                float og = sig_ap(zo);
                int ci = r01 * 2 + e;
                c[ci] = fmaf(fg, c[ci], ig * gg);
                float ca = (ACT == 0) ? tanh_ap(c[ci]) : sig_ap(c[ci]);
                hv[e] = og * ca;
            }
            __nv_bfloat16 q0 = __float2bfloat16(hv[0]);
            __nv_bfloat16 q1 = __float2bfloat16(hv[1]);
            u32 hip = ((u32)__bfloat16_as_ushort(q1) << 16) | __bfloat16_as_ushort(q0);
            u32 lop = cvt2bf(hv[0] - __bfloat162float(q0),
                             hv[1] - __bfloat162float(q1));
            int row_s = r + 8 * r01;
            u32 hoff = (u32)(row_s * A_PITCH + u0 * 2);
            *(u32*)(smem + noff + hoff)        = hip;
            *(u32*)(smem + noff + 2304 + hoff) = lop;
            *(float2*)(hout + ((size_t)(b0 + row_s) * TSEQ + t) * HU + u0) =
                make_float2(hv[0], hv[1]);
        }
        __syncthreads();
        buf ^= 1;
    }
}

// ---------------------------------------------------------------------------
// Launch
// ---------------------------------------------------------------------------
extern "C" void kernel_launch(void* const* d_in, const int* in_sizes, int n_in,
                              void* d_out, int out_size)
{
    const float* x  = (const float*)d_in[0];
    const float* W1 = (const float*)d_in[1];
    const float* U1 = (const float*)d_in[2];
    const float* b1 = (const float*)d_in[3];
    const float* W2 = (const float*)d_in[4];
    const float* U2 = (const float*)d_in[5];
    const float* b2 = (const float*)d_in[6];
    float* out = (float*)d_out;

    void *xz_p = nullptr, *h1_p = nullptr;
    cudaGetSymbolAddress(&xz_p, g_xz);
    cudaGetSymbolAddress(&h1_p, g_h1);
    float* xz = (float*)xz_p;
    float* h1 = (float*)h1_p;

    cudaFuncSetAttribute(gemm_tc_kernel<128>,
                         cudaFuncAttributeMaxDynamicSharedMemorySize, GEMM_SMEM);
    cudaFuncSetAttribute(gemm_tc_kernel<64>,
                         cudaFuncAttributeMaxDynamicSharedMemorySize, GEMM_SMEM);
    cudaFuncSetAttribute(lstm_rec_mma<0>,
                         cudaFuncAttributeMaxDynamicSharedMemorySize, REC_SMEM);
    cudaFuncSetAttribute(lstm_rec_mma<1>,
                         cudaFuncAttributeMaxDynamicSharedMemorySize, REC_SMEM);

    dim3 ggrid(MTOT / 128, 2);

    // Layer 1
    gemm_tc_kernel<128><<<ggrid, 256, GEMM_SMEM>>>(x, W1, b1, xz);
    lstm_rec_mma<0><<<BATCH / 16, 256, REC_SMEM>>>(xz, U1, h1);

    // Layer 2 (input = h1, K=64)
    gemm_tc_kernel<64><<<ggrid, 256, GEMM_SMEM>>>(h1, W2, b2, xz);
    lstm_rec_mma<1><<<BATCH / 16, 256, REC_SMEM>>>(xz, U2, out);
}